// round 6
// baseline (speedup 1.0000x reference)
#include <cuda_runtime.h>
#include <cuda_bf16.h>
#include <cstdint>

#define D_MODEL   1024
#define NUM_HEADS 16
#define D_HEAD    64
#define BATCH     2
#define SEQ       2048
#define ROWS      (BATCH * SEQ)   // 4096

// ---------------------------------------------------------------------------
// Scratch (alloc-free rule: __device__ globals)
// ---------------------------------------------------------------------------
__device__ __nv_bfloat16 g_qkvh[(size_t)ROWS * 3 * D_MODEL];
__device__ __nv_bfloat16 g_qkvl[(size_t)ROWS * 3 * D_MODEL];

__device__ __nv_bfloat16 g_xh[(size_t)ROWS * D_MODEL];
__device__ __nv_bfloat16 g_xl[(size_t)ROWS * D_MODEL];
__device__ __nv_bfloat16 g_w1h[(size_t)3 * D_MODEL * D_MODEL];
__device__ __nv_bfloat16 g_w1l[(size_t)3 * D_MODEL * D_MODEL];
__device__ __nv_bfloat16 g_w2h[(size_t)D_MODEL * D_MODEL];
__device__ __nv_bfloat16 g_w2l[(size_t)D_MODEL * D_MODEL];
__device__ __nv_bfloat16 g_yh[(size_t)ROWS * D_MODEL];
__device__ __nv_bfloat16 g_yl[(size_t)ROWS * D_MODEL];

// ---------------------------------------------------------------------------
__device__ __forceinline__ uint32_t smem_u32(const void* p) {
    uint32_t a;
    asm("{ .reg .u64 t; cvta.to.shared.u64 t, %1; cvt.u32.u64 %0, t; }"
        : "=r"(a) : "l"(p));
    return a;
}

__device__ __forceinline__ void cp_async16(uint32_t dst, const void* src) {
    asm volatile("cp.async.cg.shared.global [%0], [%1], 16;" :: "r"(dst), "l"(src));
}

__device__ __forceinline__ void mma16816(float* c, const uint32_t* a, const uint32_t* b) {
    asm volatile(
        "mma.sync.aligned.m16n8k16.row.col.f32.bf16.bf16.f32 "
        "{%0,%1,%2,%3}, {%4,%5,%6,%7}, {%8,%9}, {%0,%1,%2,%3};"
        : "+f"(c[0]), "+f"(c[1]), "+f"(c[2]), "+f"(c[3])
        : "r"(a[0]), "r"(a[1]), "r"(a[2]), "r"(a[3]), "r"(b[0]), "r"(b[1]));
}

__device__ __forceinline__ void ldsm_x4(uint32_t* r, uint32_t addr) {
    asm volatile("ldmatrix.sync.aligned.m8n8.x4.shared.b16 {%0,%1,%2,%3}, [%4];"
        : "=r"(r[0]), "=r"(r[1]), "=r"(r[2]), "=r"(r[3]) : "r"(addr));
}

__device__ __forceinline__ void ldsm_x4_t(uint32_t* r, uint32_t addr) {
    asm volatile("ldmatrix.sync.aligned.m8n8.x4.trans.shared.b16 {%0,%1,%2,%3}, [%4];"
        : "=r"(r[0]), "=r"(r[1]), "=r"(r[2]), "=r"(r[3]) : "r"(addr));
}

// pack two fp32 -> bf16x2 hi word + exact residual lo word
__device__ __forceinline__ void pack_hilo(float x, float y, uint32_t& hp, uint32_t& lp) {
    asm("cvt.rn.bf16x2.f32 %0, %1, %2;" : "=r"(hp) : "f"(y), "f"(x));
    float xh = __uint_as_float(hp << 16);
    float yh = __uint_as_float(hp & 0xffff0000u);
    float xl = x - xh;
    float yl = y - yh;
    asm("cvt.rn.bf16x2.f32 %0, %1, %2;" : "=r"(lp) : "f"(yl), "f"(xl));
}

// ---------------------------------------------------------------------------
// Split fp32 -> bf16 hi/lo; first scale4_until float4s scaled by 0.125 (exact)
// ---------------------------------------------------------------------------
__global__ __launch_bounds__(256) void split_bf16(const float* __restrict__ src,
                                                  __nv_bfloat16* __restrict__ hi,
                                                  __nv_bfloat16* __restrict__ lo,
                                                  int n4, int scale4_until) {
    int i = blockIdx.x * blockDim.x + threadIdx.x;
    if (i >= n4) return;
    float sc = (i < scale4_until) ? 0.125f : 1.0f;
    float4 v = ((const float4*)src)[i];
    float f[4] = {v.x * sc, v.y * sc, v.z * sc, v.w * sc};
    __nv_bfloat16 h[4], l[4];
#pragma unroll
    for (int j = 0; j < 4; j++) {
        h[j] = __float2bfloat16(f[j]);
        l[j] = __float2bfloat16(f[j] - __bfloat162float(h[j]));
    }
    ((uint2*)hi)[i] = *(uint2*)h;
    ((uint2*)lo)[i] = *(uint2*)l;
}

// ---------------------------------------------------------------------------
// Tensor-core GEMM NT via mma.sync (bf16, 3-term hi/lo):
//   C[m,n] = sum_k A[m,k]*B[n,k]
// Block 128x128, BK=32, 8 warps, 2-stage cp.async, ldmatrix, 2 CTAs/SM.
// Term-major MMA ordering (same-acc distance 4) for tensor-pipe ILP.
// BF16OUT: write bf16 hi/lo (feeds attention) instead of fp32.
// ---------------------------------------------------------------------------
#define BKG        32
#define SROW       40
#define TILE_ELEM  (128 * SROW)
#define STAGE_ELEM (4 * TILE_ELEM)
#define NSTAGE     2
#define GEMM_SMEM  (NSTAGE * STAGE_ELEM * 2)   // 81920 B

__device__ __forceinline__ void load_stage(uint32_t s_base,
                                           const __nv_bfloat16* Ah, const __nv_bfloat16* Al,
                                           const __nv_bfloat16* Bh, const __nv_bfloat16* Bl,
                                           int m0, int n0, int k0, int K, int tid) {
#pragma unroll
    for (int p = 0; p < 2; p++) {
        int v = tid + p * 256;
        int row = v >> 2;
        int c = v & 3;
        uint32_t soff = (uint32_t)(row * (SROW * 2) + c * 16);
        cp_async16(s_base + soff,
                   (const char*)(Ah + (size_t)(m0 + row) * K + k0) + c * 16);
        cp_async16(s_base + TILE_ELEM * 2 + soff,
                   (const char*)(Al + (size_t)(m0 + row) * K + k0) + c * 16);
        cp_async16(s_base + 2 * TILE_ELEM * 2 + soff,
                   (const char*)(Bh + (size_t)(n0 + row) * K + k0) + c * 16);
        cp_async16(s_base + 3 * TILE_ELEM * 2 + soff,
                   (const char*)(Bl + (size_t)(n0 + row) * K + k0) + c * 16);
    }
}

template <bool BF16OUT>
__global__ __launch_bounds__(256, 2) void gemm_tc(const __nv_bfloat16* __restrict__ Ah,
                                                  const __nv_bfloat16* __restrict__ Al,
                                                  const __nv_bfloat16* __restrict__ Bh,
                                                  const __nv_bfloat16* __restrict__ Bl,
                                                  float* __restrict__ C,
                                                  __nv_bfloat16* __restrict__ Ch,
                                                  __nv_bfloat16* __restrict__ Cl,
                                                  int M, int N, int K) {
    extern __shared__ __nv_bfloat16 smem[];
    const uint32_t sbase = smem_u32(smem);

    const int tid = threadIdx.x;
    const int wid = tid >> 5;
    const int lane = tid & 31;
    const int g = lane >> 2;
    const int t = lane & 3;
    const int m0 = blockIdx.y * 128;
    const int n0 = blockIdx.x * 128;
    const int wm = (wid >> 2) * 64;
    const int wn = (wid & 3) * 32;

    const int lrow  = (lane & 7) + 8 * ((lane >> 3) & 1);
    const int lcol8 = 8 * (lane >> 4);
    const int lrowK = (lane & 7) + 8 * (lane >> 4);
    const int lcol8K = 8 * ((lane >> 3) & 1);

    float acc[4][4][4];
#pragma unroll
    for (int mi = 0; mi < 4; mi++)
#pragma unroll
        for (int ni = 0; ni < 4; ni++)
#pragma unroll
            for (int r = 0; r < 4; r++) acc[mi][ni][r] = 0.f;

    const int NIT = K / BKG;

    load_stage(sbase, Ah, Al, Bh, Bl, m0, n0, 0, K, tid);
    asm volatile("cp.async.commit_group;" ::: "memory");

    for (int it = 0; it < NIT; it++) {
        if (it + 1 < NIT) {
            load_stage(sbase + ((it + 1) & 1) * STAGE_ELEM * 2, Ah, Al, Bh, Bl,
                       m0, n0, (it + 1) * BKG, K, tid);
        }
        asm volatile("cp.async.commit_group;" ::: "memory");
        asm volatile("cp.async.wait_group 1;" ::: "memory");
        __syncthreads();

        const uint32_t sAh = sbase + (it & 1) * STAGE_ELEM * 2;
        const uint32_t sAl = sAh + TILE_ELEM * 2;
        const uint32_t sBh = sAh + 2 * TILE_ELEM * 2;
        const uint32_t sBl = sAh + 3 * TILE_ELEM * 2;

#pragma unroll
        for (int ks = 0; ks < 2; ks++) {
            const int kb = ks * 16;
            uint32_t bh[2][4], bl[2][4];
#pragma unroll
            for (int np = 0; np < 2; np++) {
                uint32_t boff = (uint32_t)((wn + np * 16 + lrowK) * (SROW * 2)
                                           + (kb + lcol8K) * 2);
                ldsm_x4(bh[np], sBh + boff);
                ldsm_x4(bl[np], sBl + boff);
            }
#pragma unroll
            for (int mi = 0; mi < 4; mi++) {
                uint32_t ah[4], al[4];
                uint32_t aoff = (uint32_t)((wm + mi * 16 + lrow) * (SROW * 2)
                                           + (kb + lcol8) * 2);
                ldsm_x4(ah, sAh + aoff);
                ldsm_x4(al, sAl + aoff);
                // term-major ordering: same-acc RAW distance = 4 MMAs
#pragma unroll
                for (int np = 0; np < 2; np++) {
                    mma16816(acc[mi][2 * np],     ah, bh[np]);
                    mma16816(acc[mi][2 * np + 1], ah, bh[np] + 2);
                }
#pragma unroll
                for (int np = 0; np < 2; np++) {
                    mma16816(acc[mi][2 * np],     ah, bl[np]);
                    mma16816(acc[mi][2 * np + 1], ah, bl[np] + 2);
                }
#pragma unroll
                for (int np = 0; np < 2; np++) {
                    mma16816(acc[mi][2 * np],     al, bh[np]);
                    mma16816(acc[mi][2 * np + 1], al, bh[np] + 2);
                }
            }
        }
        __syncthreads();
    }

#pragma unroll
    for (int mi = 0; mi < 4; mi++) {
        int row0 = m0 + wm + mi * 16 + g;
#pragma unroll
        for (int ni = 0; ni < 4; ni++) {
            int col = n0 + wn + ni * 8 + 2 * t;
            if (BF16OUT) {
                uint32_t hp, lp;
                pack_hilo(acc[mi][ni][0], acc[mi][ni][1], hp, lp);
                *(uint32_t*)&Ch[(size_t)row0 * N + col] = hp;
                *(uint32_t*)&Cl[(size_t)row0 * N + col] = lp;
                pack_hilo(acc[mi][ni][2], acc[mi][ni][3], hp, lp);
                *(uint32_t*)&Ch[(size_t)(row0 + 8) * N + col] = hp;
                *(uint32_t*)&Cl[(size_t)(row0 + 8) * N + col] = lp;
            } else {
                *(float2*)&C[(size_t)row0 * N + col] =
                    make_float2(acc[mi][ni][0], acc[mi][ni][1]);
                *(float2*)&C[(size_t)(row0 + 8) * N + col] =
                    make_float2(acc[mi][ni][2], acc[mi][ni][3]);
            }
        }
    }
}

// ---------------------------------------------------------------------------
// Tensor-core causal flash attention. BQ=128, BK=64, Dh=64, 256 threads.
// Q/K/V come in PRE-SPLIT bf16 hi/lo (from the QKV projection) -> pure
// cp.async tile loads, no in-kernel conversion. Q pre-scaled via Wqkv.
// ---------------------------------------------------------------------------
#define AT_SMEM 73728

__global__ __launch_bounds__(256) void attn_tc(const __nv_bfloat16* __restrict__ qkvh,
                                               const __nv_bfloat16* __restrict__ qkvl,
                                               __nv_bfloat16* __restrict__ yh,
                                               __nv_bfloat16* __restrict__ yl) {
    extern __shared__ __nv_bfloat16 asmem[];
    const uint32_t sb = smem_u32(asmem);
    const uint32_t QH = sb, QL = sb + 18432, KH = sb + 36864, KL = sb + 46080,
                   VH = sb + 55296, VL = sb + 64512;

    const int tid = threadIdx.x;
    const int wid = tid >> 5;
    const int lane = tid & 31;
    const int g = lane >> 2, t = lane & 3;
    const int qt = blockIdx.x, h = blockIdx.y, b = blockIdx.z;
    const int q0 = qt * 128;

    const size_t rowstride = 3 * D_MODEL;
    const __nv_bfloat16* qh = qkvh + (size_t)b * SEQ * rowstride + h * D_HEAD;
    const __nv_bfloat16* ql = qkvl + (size_t)b * SEQ * rowstride + h * D_HEAD;
    const __nv_bfloat16* kh = qh + D_MODEL;
    const __nv_bfloat16* kl = ql + D_MODEL;
    const __nv_bfloat16* vh = qh + 2 * D_MODEL;
    const __nv_bfloat16* vl = ql + 2 * D_MODEL;

    const int lrow  = (lane & 7) + 8 * ((lane >> 3) & 1);
    const int lcol8 = 8 * (lane >> 4);
    const int lrowK = (lane & 7) + 8 * (lane >> 4);
    const int lcol8K = 8 * ((lane >> 3) & 1);

    // ---- async-load Q tile (128 rows x 64 cols, hi+lo) ----
#pragma unroll
    for (int p = 0; p < 8; p++) {
        int v = tid + p * 256;          // 0..2047
        int row = v >> 4, c = v & 15;
        if (c < 8)
            cp_async16(QH + row * 144 + c * 16, qh + (size_t)(q0 + row) * rowstride + c * 8);
        else
            cp_async16(QL + row * 144 + (c - 8) * 16,
                       ql + (size_t)(q0 + row) * rowstride + (c - 8) * 8);
    }
    asm volatile("cp.async.commit_group;" ::: "memory");

    float m_[2] = {-1e30f, -1e30f};
    float l_[2] = {0.f, 0.f};
    float o[8][4];
#pragma unroll
    for (int nt = 0; nt < 8; nt++)
#pragma unroll
        for (int c = 0; c < 4; c++) o[nt][c] = 0.f;

    const int ntiles = 2 * qt + 2;
    for (int kt = 0; kt < ntiles; kt++) {
        __syncthreads();   // previous iteration's ldmatrix done with K/V smem

        // ---- async-load K,V tiles (64 rows x 64 cols each, hi+lo) ----
#pragma unroll
        for (int p = 0; p < 8; p++) {
            int v = tid + p * 256;       // 0..2047
            int tensor = v >> 10;        // 0 = K, 1 = V
            int w = v & 1023;
            int row = w >> 4, c = w & 15;
            size_t goff = (size_t)(kt * 64 + row) * rowstride + (c & 7) * 8;
            if (tensor == 0) {
                if (c < 8) cp_async16(KH + row * 144 + c * 16, kh + goff);
                else       cp_async16(KL + row * 144 + (c - 8) * 16, kl + goff);
            } else {
                if (c < 8) cp_async16(VH + row * 144 + c * 16, vh + goff);
                else       cp_async16(VL + row * 144 + (c - 8) * 16, vl + goff);
            }
        }
        asm volatile("cp.async.commit_group;" ::: "memory");
        asm volatile("cp.async.wait_group 0;" ::: "memory");
        __syncthreads();

        // ---- S = Q K^T ----
        float s[8][4];
#pragma unroll
        for (int nt = 0; nt < 8; nt++)
#pragma unroll
            for (int c = 0; c < 4; c++) s[nt][c] = 0.f;

#pragma unroll
        for (int ks = 0; ks < 4; ks++) {
            uint32_t ah[4], al[4];
            uint32_t qoff = (uint32_t)((wid * 16 + lrow) * 144 + (ks * 16 + lcol8) * 2);
            ldsm_x4(ah, QH + qoff);
            ldsm_x4(al, QL + qoff);
#pragma unroll
            for (int ntp = 0; ntp < 4; ntp++) {
                uint32_t bh[4], bl[4];
                uint32_t koff = (uint32_t)((ntp * 16 + lrowK) * 144 + (ks * 16 + lcol8K) * 2);
                ldsm_x4(bh, KH + koff);
                ldsm_x4(bl, KL + koff);
                mma16816(s[2 * ntp],     ah, bh);
                mma16816(s[2 * ntp + 1], ah, bh + 2);
                mma16816(s[2 * ntp],     ah, bl);
                mma16816(s[2 * ntp + 1], ah, bl + 2);
                mma16816(s[2 * ntp],     al, bh);
                mma16816(s[2 * ntp + 1], al, bh + 2);
            }
        }

        if (kt >= 2 * qt) {
#pragma unroll
            for (int nt = 0; nt < 8; nt++)
#pragma unroll
                for (int c = 0; c < 4; c++) {
                    int row = q0 + wid * 16 + g + (c >> 1) * 8;
                    int col = kt * 64 + nt * 8 + 2 * t + (c & 1);
                    if (col > row) s[nt][c] = -1e30f;
                }
        }

#pragma unroll
        for (int r = 0; r < 2; r++) {
            float mx = -1e30f;
#pragma unroll
            for (int nt = 0; nt < 8; nt++)
                mx = fmaxf(mx, fmaxf(s[nt][2 * r], s[nt][2 * r + 1]));
            mx = fmaxf(mx, __shfl_xor_sync(0xffffffffu, mx, 1));
            mx = fmaxf(mx, __shfl_xor_sync(0xffffffffu, mx, 2));
            float mnew = fmaxf(m_[r], mx);
            float corr = __expf(m_[r] - mnew);
            m_[r] = mnew;
            float ls = 0.f;
#pragma unroll
            for (int nt = 0; nt < 8; nt++) {
                float p0 = __expf(s[nt][2 * r] - mnew);
                float p1 = __expf(s[nt][2 * r + 1] - mnew);
                s[nt][2 * r] = p0;
                s[nt][2 * r + 1] = p1;
                ls += p0 + p1;
            }
            ls += __shfl_xor_sync(0xffffffffu, ls, 1);
            ls += __shfl_xor_sync(0xffffffffu, ls, 2);
            l_[r] = l_[r] * corr + ls;
#pragma unroll
            for (int nt = 0; nt < 8; nt++) {
                o[nt][2 * r] *= corr;
                o[nt][2 * r + 1] *= corr;
            }
        }

        // ---- O += P V ----
#pragma unroll
        for (int kc = 0; kc < 4; kc++) {
            uint32_t ah[4], al[4];
            pack_hilo(s[2 * kc][0],     s[2 * kc][1],     ah[0], al[0]);
            pack_hilo(s[2 * kc][2],     s[2 * kc][3],     ah[1], al[1]);
            pack_hilo(s[2 * kc + 1][0], s[2 * kc + 1][1], ah[2], al[2]);
            pack_hilo(s[2 * kc + 1][2], s[2 * kc + 1][3], ah[3], al[3]);
#pragma unroll
            for (int ntp = 0; ntp < 4; ntp++) {
                uint32_t bh[4], bl[4];
                uint32_t voff = (uint32_t)((kc * 16 + lrow) * 144 + (ntp * 16 + lcol8) * 2);
                ldsm_x4_t(bh, VH + voff);
                ldsm_x4_t(bl, VL + voff);
                mma16816(o[2 * ntp],     ah, bh);
                mma16816(o[2 * ntp + 1], ah, bh + 2);
                mma16816(o[2 * ntp],     ah, bl);
                mma16816(o[2 * ntp + 1], ah, bl + 2);
                mma16816(o[2 * ntp],     al, bh);
                mma16816(o[2 * ntp + 1], al, bh + 2);
            }
        }
    }

    // ---- epilogue: normalize + write y as bf16 hi/lo ----
    {
        float inv0 = 1.f / l_[0];
        float inv1 = 1.f / l_[1];
        int row0 = q0 + wid * 16 + g;
        size_t t0 = (size_t)b * SEQ + row0;
#pragma unroll
        for (int nt = 0; nt < 8; nt++) {
            int col = h * D_HEAD + nt * 8 + 2 * t;
            uint32_t hp, lp;
            pack_hilo(o[nt][0] * inv0, o[nt][1] * inv0, hp, lp);
            *(uint32_t*)&yh[t0 * D_MODEL + col] = hp;
            *(uint32_t*)&yl[t0 * D_MODEL + col] = lp;
            pack_hilo(o[nt][2] * inv1, o[nt][3] * inv1, hp, lp);
            *(uint32_t*)&yh[(t0 + 8) * D_MODEL + col] = hp;
            *(uint32_t*)&yl[(t0 + 8) * D_MODEL + col] = lp;
        }
    }
}

// ---------------------------------------------------------------------------
extern "C" void kernel_launch(void* const* d_in, const int* in_sizes, int n_in,
                              void* d_out, int out_size) {
    const float* x    = (const float*)d_in[0];
    const float* Wqkv = (const float*)d_in[1];
    const float* Wout = (const float*)d_in[2];
    float* out = (float*)d_out;

    __nv_bfloat16 *qkvh, *qkvl, *xh, *xl, *w1h, *w1l, *w2h, *w2l, *yh, *yl;
    cudaGetSymbolAddress((void**)&qkvh, g_qkvh);
    cudaGetSymbolAddress((void**)&qkvl, g_qkvl);
    cudaGetSymbolAddress((void**)&xh, g_xh);
    cudaGetSymbolAddress((void**)&xl, g_xl);
    cudaGetSymbolAddress((void**)&w1h, g_w1h);
    cudaGetSymbolAddress((void**)&w1l, g_w1l);
    cudaGetSymbolAddress((void**)&w2h, g_w2h);
    cudaGetSymbolAddress((void**)&w2l, g_w2l);
    cudaGetSymbolAddress((void**)&yh, g_yh);
    cudaGetSymbolAddress((void**)&yl, g_yl);

    cudaFuncSetAttribute(gemm_tc<true>, cudaFuncAttributeMaxDynamicSharedMemorySize, GEMM_SMEM);
    cudaFuncSetAttribute(gemm_tc<false>, cudaFuncAttributeMaxDynamicSharedMemorySize, GEMM_SMEM);
    cudaFuncSetAttribute(attn_tc, cudaFuncAttributeMaxDynamicSharedMemorySize, AT_SMEM);

    // Splits (Wqkv Q-rows pre-scaled by 1/8 = attention scale, exact)
    {
        int n4 = ROWS * D_MODEL / 4;
        split_bf16<<<(n4 + 255) / 256, 256>>>(x, xh, xl, n4, 0);
        int w1n4 = 3 * D_MODEL * D_MODEL / 4;
        split_bf16<<<(w1n4 + 255) / 256, 256>>>(Wqkv, w1h, w1l, w1n4,
                                                D_MODEL * D_MODEL / 4);
        int w2n4 = D_MODEL * D_MODEL / 4;
        split_bf16<<<(w2n4 + 255) / 256, 256>>>(Wout, w2h, w2l, w2n4, 0);
    }

    // 1) QKV projection -> bf16 hi/lo qkv
    gemm_tc<true><<<dim3(3 * D_MODEL / 128, ROWS / 128), 256, GEMM_SMEM>>>(
        xh, xl, w1h, w1l, nullptr, qkvh, qkvl, ROWS, 3 * D_MODEL, D_MODEL);

    // 2) Tensor-core causal flash attention -> yh/yl bf16 hi/lo
    attn_tc<<<dim3(SEQ / 128, NUM_HEADS, BATCH), 256, AT_SMEM>>>(qkvh, qkvl, yh, yl);

    // 3) Output projection -> fp32 out
    gemm_tc<false><<<dim3(D_MODEL / 128, ROWS / 128), 256, GEMM_SMEM>>>(
        yh, yl, w2h, w2l, out, nullptr, nullptr, ROWS, D_MODEL, D_MODEL);
}

// round 7
// speedup vs baseline: 1.2413x; 1.2413x over previous
#include <cuda_runtime.h>
#include <cuda_bf16.h>
#include <cuda_fp16.h>
#include <cstdint>

#define D_MODEL   1024
#define NUM_HEADS 16
#define D_HEAD    64
#define BATCH     2
#define SEQ       2048
#define ROWS      (BATCH * SEQ)   // 4096

// ---------------------------------------------------------------------------
// Scratch (alloc-free rule: __device__ globals)
// ---------------------------------------------------------------------------
__device__ float g_qkv[(size_t)ROWS * 3 * D_MODEL];     // fp32 QKV (GEMM1 out)

__device__ __half g_xf[(size_t)ROWS * D_MODEL];          // x as fp16
__device__ __half g_w1h[(size_t)3 * D_MODEL * D_MODEL];  // Wqkv hi (x64, Q rows x8)
__device__ __half g_w1l[(size_t)3 * D_MODEL * D_MODEL];  // Wqkv lo
__device__ __half g_w2h[(size_t)D_MODEL * D_MODEL];      // Wout hi (x64)
__device__ __half g_w2l[(size_t)D_MODEL * D_MODEL];      // Wout lo
__device__ __half g_yf[(size_t)ROWS * D_MODEL];          // attention out, fp16

// ---------------------------------------------------------------------------
__device__ __forceinline__ uint32_t smem_u32(const void* p) {
    uint32_t a;
    asm("{ .reg .u64 t; cvta.to.shared.u64 t, %1; cvt.u32.u64 %0, t; }"
        : "=r"(a) : "l"(p));
    return a;
}

__device__ __forceinline__ void cp_async16(uint32_t dst, const void* src) {
    asm volatile("cp.async.cg.shared.global [%0], [%1], 16;" :: "r"(dst), "l"(src));
}

// bf16 MMA (attention)
__device__ __forceinline__ void mma16816(float* c, const uint32_t* a, const uint32_t* b) {
    asm volatile(
        "mma.sync.aligned.m16n8k16.row.col.f32.bf16.bf16.f32 "
        "{%0,%1,%2,%3}, {%4,%5,%6,%7}, {%8,%9}, {%0,%1,%2,%3};"
        : "+f"(c[0]), "+f"(c[1]), "+f"(c[2]), "+f"(c[3])
        : "r"(a[0]), "r"(a[1]), "r"(a[2]), "r"(a[3]), "r"(b[0]), "r"(b[1]));
}

// fp16 MMA (projections)
__device__ __forceinline__ void mma16816h(float* c, const uint32_t* a, const uint32_t* b) {
    asm volatile(
        "mma.sync.aligned.m16n8k16.row.col.f32.f16.f16.f32 "
        "{%0,%1,%2,%3}, {%4,%5,%6,%7}, {%8,%9}, {%0,%1,%2,%3};"
        : "+f"(c[0]), "+f"(c[1]), "+f"(c[2]), "+f"(c[3])
        : "r"(a[0]), "r"(a[1]), "r"(a[2]), "r"(a[3]), "r"(b[0]), "r"(b[1]));
}

__device__ __forceinline__ void ldsm_x4(uint32_t* r, uint32_t addr) {
    asm volatile("ldmatrix.sync.aligned.m8n8.x4.shared.b16 {%0,%1,%2,%3}, [%4];"
        : "=r"(r[0]), "=r"(r[1]), "=r"(r[2]), "=r"(r[3]) : "r"(addr));
}

__device__ __forceinline__ void ldsm_x4_t(uint32_t* r, uint32_t addr) {
    asm volatile("ldmatrix.sync.aligned.m8n8.x4.trans.shared.b16 {%0,%1,%2,%3}, [%4];"
        : "=r"(r[0]), "=r"(r[1]), "=r"(r[2]), "=r"(r[3]) : "r"(addr));
}

// pack two fp32 -> bf16x2 hi word + exact residual lo word (lo half = x)
__device__ __forceinline__ void pack_hilo(float x, float y, uint32_t& hp, uint32_t& lp) {
    asm("cvt.rn.bf16x2.f32 %0, %1, %2;" : "=r"(hp) : "f"(y), "f"(x));
    float xh = __uint_as_float(hp << 16);
    float yh = __uint_as_float(hp & 0xffff0000u);
    float xl = x - xh;
    float yl = y - yh;
    asm("cvt.rn.bf16x2.f32 %0, %1, %2;" : "=r"(lp) : "f"(yl), "f"(xl));
}

__device__ __forceinline__ uint32_t pack_f16x2(float x, float y) {
    uint32_t r;
    asm("cvt.rn.f16x2.f32 %0, %1, %2;" : "=r"(r) : "f"(y), "f"(x));
    return r;
}

// split a float4 into hi/lo bf16 quads and store (8 B each) to smem
__device__ __forceinline__ void split_store4(uint32_t sh, uint32_t sl, float4 v) {
    uint32_t h0, h1, l0, l1;
    pack_hilo(v.x, v.y, h0, l0);
    pack_hilo(v.z, v.w, h1, l1);
    asm volatile("st.shared.v2.u32 [%0], {%1,%2};" :: "r"(sh), "r"(h0), "r"(h1));
    asm volatile("st.shared.v2.u32 [%0], {%1,%2};" :: "r"(sl), "r"(l0), "r"(l1));
}

// ---------------------------------------------------------------------------
// fp32 -> fp16 single convert
// ---------------------------------------------------------------------------
__global__ __launch_bounds__(256) void conv_f16(const float* __restrict__ src,
                                                __half* __restrict__ dst, int n4) {
    int i = blockIdx.x * blockDim.x + threadIdx.x;
    if (i >= n4) return;
    float4 v = ((const float4*)src)[i];
    uint32_t p0 = pack_f16x2(v.x, v.y);
    uint32_t p1 = pack_f16x2(v.z, v.w);
    ((uint2*)dst)[i] = make_uint2(p0, p1);
}

// fp32 -> fp16 hi/lo split with per-region scale (Q rows x8, rest x64)
__global__ __launch_bounds__(256) void split_f16w(const float* __restrict__ src,
                                                  __half* __restrict__ hi,
                                                  __half* __restrict__ lo,
                                                  int n4, int q4_until) {
    int i = blockIdx.x * blockDim.x + threadIdx.x;
    if (i >= n4) return;
    float sc = (i < q4_until) ? 8.0f : 64.0f;
    float4 v = ((const float4*)src)[i];
    float f[4] = {v.x * sc, v.y * sc, v.z * sc, v.w * sc};
    __half h[4], l[4];
#pragma unroll
    for (int j = 0; j < 4; j++) {
        h[j] = __float2half_rn(f[j]);
        l[j] = __float2half_rn(f[j] - __half2float(h[j]));
    }
    ((uint2*)hi)[i] = *(uint2*)h;
    ((uint2*)lo)[i] = *(uint2*)l;
}

// ---------------------------------------------------------------------------
// fp16 2-term GEMM NT via mma.sync:
//   C[m,n] = (1/64) * sum_k A[m,k]*(Bh[n,k]+Bl[n,k])
// Block 128x128, BK=32, 8 warps (warp 64x32), 3-stage cp.async, 2 CTAs/SM.
// ---------------------------------------------------------------------------
#define SROW       40                    // fp16 elems per smem row (80 B)
#define TILE_B     (128 * SROW * 2)      // 10240 B per tile
#define STAGE_B    (3 * TILE_B)          // A, Bh, Bl = 30720 B
#define NSTAGE     3
#define GEMM_SMEM  (NSTAGE * STAGE_B)    // 92160 B

__device__ __forceinline__ void load_stage(uint32_t s_base,
                                           const __half* Af,
                                           const __half* Bh, const __half* Bl,
                                           int m0, int n0, int k0, int K, int tid) {
#pragma unroll
    for (int p = 0; p < 2; p++) {
        int v = tid + p * 256;
        int row = v >> 2;
        int c = v & 3;
        uint32_t soff = (uint32_t)(row * (SROW * 2) + c * 16);
        cp_async16(s_base + soff,
                   Af + (size_t)(m0 + row) * K + k0 + c * 8);
        cp_async16(s_base + TILE_B + soff,
                   Bh + (size_t)(n0 + row) * K + k0 + c * 8);
        cp_async16(s_base + 2 * TILE_B + soff,
                   Bl + (size_t)(n0 + row) * K + k0 + c * 8);
    }
}

__global__ __launch_bounds__(256, 2) void gemm_f16(const __half* __restrict__ Af,
                                                   const __half* __restrict__ Bh,
                                                   const __half* __restrict__ Bl,
                                                   float* __restrict__ C,
                                                   int M, int N, int K) {
    extern __shared__ __half smem[];
    const uint32_t sbase = smem_u32(smem);

    const int tid = threadIdx.x;
    const int wid = tid >> 5;
    const int lane = tid & 31;
    const int g = lane >> 2;
    const int t = lane & 3;
    const int m0 = blockIdx.y * 128;
    const int n0 = blockIdx.x * 128;
    const int wm = (wid >> 2) * 64;
    const int wn = (wid & 3) * 32;

    const int lrow  = (lane & 7) + 8 * ((lane >> 3) & 1);   // A frag
    const int lcol8 = 8 * (lane >> 4);
    const int lrowK = (lane & 7) + 8 * (lane >> 4);          // B frag
    const int lcol8K = 8 * ((lane >> 3) & 1);

    float acc[4][4][4];
#pragma unroll
    for (int mi = 0; mi < 4; mi++)
#pragma unroll
        for (int ni = 0; ni < 4; ni++)
#pragma unroll
            for (int r = 0; r < 4; r++) acc[mi][ni][r] = 0.f;

    const int NIT = K / 32;   // 32

    // Prologue: stages 0,1
    load_stage(sbase, Af, Bh, Bl, m0, n0, 0, K, tid);
    asm volatile("cp.async.commit_group;" ::: "memory");
    load_stage(sbase + STAGE_B, Af, Bh, Bl, m0, n0, 32, K, tid);
    asm volatile("cp.async.commit_group;" ::: "memory");

    for (int it = 0; it < NIT; it++) {
        if (it + 2 < NIT) {
            load_stage(sbase + ((it + 2) % NSTAGE) * STAGE_B, Af, Bh, Bl,
                       m0, n0, (it + 2) * 32, K, tid);
        }
        asm volatile("cp.async.commit_group;" ::: "memory");
        asm volatile("cp.async.wait_group 2;" ::: "memory");
        __syncthreads();

        const uint32_t sA  = sbase + (it % NSTAGE) * STAGE_B;
        const uint32_t sBh = sA + TILE_B;
        const uint32_t sBl = sA + 2 * TILE_B;

#pragma unroll
        for (int ks = 0; ks < 2; ks++) {
            const int kb = ks * 16;
            uint32_t bh[2][4], bl[2][4];
#pragma unroll
            for (int np = 0; np < 2; np++) {
                uint32_t boff = (uint32_t)((wn + np * 16 + lrowK) * (SROW * 2)
                                           + (kb + lcol8K) * 2);
                ldsm_x4(bh[np], sBh + boff);
                ldsm_x4(bl[np], sBl + boff);
            }
#pragma unroll
            for (int mi = 0; mi < 4; mi++) {
                uint32_t ah[4];
                uint32_t aoff = (uint32_t)((wm + mi * 16 + lrow) * (SROW * 2)
                                           + (kb + lcol8) * 2);
                ldsm_x4(ah, sA + aoff);
#pragma unroll
                for (int np = 0; np < 2; np++) {
                    mma16816h(acc[mi][2 * np],     ah, bh[np]);
                    mma16816h(acc[mi][2 * np],     ah, bl[np]);
                    mma16816h(acc[mi][2 * np + 1], ah, bh[np] + 2);
                    mma16816h(acc[mi][2 * np + 1], ah, bl[np] + 2);
                }
            }
        }
        __syncthreads();
    }

    const float cs = 1.0f / 64.0f;
#pragma unroll
    for (int mi = 0; mi < 4; mi++) {
        int row0 = m0 + wm + mi * 16 + g;
#pragma unroll
        for (int ni = 0; ni < 4; ni++) {
            int col = n0 + wn + ni * 8 + 2 * t;
            *(float2*)&C[(size_t)row0 * N + col] =
                make_float2(acc[mi][ni][0] * cs, acc[mi][ni][1] * cs);
            *(float2*)&C[(size_t)(row0 + 8) * N + col] =
                make_float2(acc[mi][ni][2] * cs, acc[mi][ni][3] * cs);
        }
    }
}

// ---------------------------------------------------------------------------
// Tensor-core causal flash attention (R5-proven). BQ=128, BK=64, Dh=64,
// 256 threads, fp32 qkv in (split to bf16 hi/lo in-kernel, 3-term MMAs).
// Epilogue writes y as single fp16 (A operand of the output projection).
// ---------------------------------------------------------------------------
#define AT_SMEM 73728

__global__ __launch_bounds__(256) void attn_tc(const float* __restrict__ qkv,
                                               __half* __restrict__ yf) {
    extern __shared__ __nv_bfloat16 asmem[];
    const uint32_t sb = smem_u32(asmem);
    const uint32_t QH = sb, QL = sb + 18432, KH = sb + 36864, KL = sb + 46080,
                   VH = sb + 55296, VL = sb + 64512;

    const int tid = threadIdx.x;
    const int wid = tid >> 5;
    const int lane = tid & 31;
    const int g = lane >> 2, t = lane & 3;
    const int qt = blockIdx.x, h = blockIdx.y, b = blockIdx.z;
    const int q0 = qt * 128;

    const size_t rowstride = 3 * D_MODEL;
    const float* qbase = qkv + (size_t)b * SEQ * rowstride + h * D_HEAD;
    const float* kbase = qbase + D_MODEL;
    const float* vbase = qbase + 2 * D_MODEL;

    const int lrow  = (lane & 7) + 8 * ((lane >> 3) & 1);
    const int lcol8 = 8 * (lane >> 4);
    const int lrowK = (lane & 7) + 8 * (lane >> 4);
    const int lcol8K = 8 * ((lane >> 3) & 1);

    // ---- load + split Q (pre-scaled via Wqkv) ----
#pragma unroll
    for (int p = 0; p < 8; p++) {
        int v = tid + p * 256;
        int row = v >> 4, c = v & 15;
        float4 q4 = *(const float4*)&qbase[(size_t)(q0 + row) * rowstride + c * 4];
        split_store4(QH + row * 144 + c * 8, QL + row * 144 + c * 8, q4);
    }

    float m_[2] = {-1e30f, -1e30f};
    float l_[2] = {0.f, 0.f};
    float o[8][4];
#pragma unroll
    for (int nt = 0; nt < 8; nt++)
#pragma unroll
        for (int c = 0; c < 4; c++) o[nt][c] = 0.f;

    const int ntiles = 2 * qt + 2;
    for (int kt = 0; kt < ntiles; kt++) {
        __syncthreads();

#pragma unroll
        for (int p = 0; p < 4; p++) {
            int v = tid + p * 256;
            int j = v >> 4, c = v & 15;
            float4 k4 = *(const float4*)&kbase[(size_t)(kt * 64 + j) * rowstride + c * 4];
            split_store4(KH + j * 144 + c * 8, KL + j * 144 + c * 8, k4);
            float4 v4 = *(const float4*)&vbase[(size_t)(kt * 64 + j) * rowstride + c * 4];
            split_store4(VH + j * 144 + c * 8, VL + j * 144 + c * 8, v4);
        }
        __syncthreads();

        float s[8][4];
#pragma unroll
        for (int nt = 0; nt < 8; nt++)
#pragma unroll
            for (int c = 0; c < 4; c++) s[nt][c] = 0.f;

#pragma unroll
        for (int ks = 0; ks < 4; ks++) {
            uint32_t ah[4], al[4];
            uint32_t qoff = (uint32_t)((wid * 16 + lrow) * 144 + (ks * 16 + lcol8) * 2);
            ldsm_x4(ah, QH + qoff);
            ldsm_x4(al, QL + qoff);
#pragma unroll
            for (int ntp = 0; ntp < 4; ntp++) {
                uint32_t bh[4], bl[4];
                uint32_t koff = (uint32_t)((ntp * 16 + lrowK) * 144 + (ks * 16 + lcol8K) * 2);
                ldsm_x4(bh, KH + koff);
                ldsm_x4(bl, KL + koff);
                mma16816(s[2 * ntp],     ah, bh);
                mma16816(s[2 * ntp],     ah, bl);
                mma16816(s[2 * ntp],     al, bh);
                mma16816(s[2 * ntp + 1], ah, bh + 2);
                mma16816(s[2 * ntp + 1], ah, bl + 2);
                mma16816(s[2 * ntp + 1], al, bh + 2);
            }
        }

        if (kt >= 2 * qt) {
#pragma unroll
            for (int nt = 0; nt < 8; nt++)
#pragma unroll
                for (int c = 0; c < 4; c++) {
                    int row = q0 + wid * 16 + g + (c >> 1) * 8;
                    int col = kt * 64 + nt * 8 + 2 * t + (c & 1);
                    if (col > row) s[nt][c] = -1e30f;
                }
        }

#pragma unroll
        for (int r = 0; r < 2; r++) {
            float mx = -1e30f;
#pragma unroll
            for (int nt = 0; nt < 8; nt++)
                mx = fmaxf(mx, fmaxf(s[nt][2 * r], s[nt][2 * r + 1]));
            mx = fmaxf(mx, __shfl_xor_sync(0xffffffffu, mx, 1));
            mx = fmaxf(mx, __shfl_xor_sync(0xffffffffu, mx, 2));
            float mnew = fmaxf(m_[r], mx);
            float corr = __expf(m_[r] - mnew);
            m_[r] = mnew;
            float ls = 0.f;
#pragma unroll
            for (int nt = 0; nt < 8; nt++) {
                float p0 = __expf(s[nt][2 * r] - mnew);
                float p1 = __expf(s[nt][2 * r + 1] - mnew);
                s[nt][2 * r] = p0;
                s[nt][2 * r + 1] = p1;
                ls += p0 + p1;
            }
            ls += __shfl_xor_sync(0xffffffffu, ls, 1);
            ls += __shfl_xor_sync(0xffffffffu, ls, 2);
            l_[r] = l_[r] * corr + ls;
#pragma unroll
            for (int nt = 0; nt < 8; nt++) {
                o[nt][2 * r] *= corr;
                o[nt][2 * r + 1] *= corr;
            }
        }

#pragma unroll
        for (int kc = 0; kc < 4; kc++) {
            uint32_t ah[4], al[4];
            pack_hilo(s[2 * kc][0],     s[2 * kc][1],     ah[0], al[0]);
            pack_hilo(s[2 * kc][2],     s[2 * kc][3],     ah[1], al[1]);
            pack_hilo(s[2 * kc + 1][0], s[2 * kc + 1][1], ah[2], al[2]);
            pack_hilo(s[2 * kc + 1][2], s[2 * kc + 1][3], ah[3], al[3]);
#pragma unroll
            for (int ntp = 0; ntp < 4; ntp++) {
                uint32_t bh[4], bl[4];
                uint32_t voff = (uint32_t)((kc * 16 + lrow) * 144 + (ntp * 16 + lcol8) * 2);
                ldsm_x4_t(bh, VH + voff);
                ldsm_x4_t(bl, VL + voff);
                mma16816(o[2 * ntp],     ah, bh);
                mma16816(o[2 * ntp],     ah, bl);
                mma16816(o[2 * ntp],     al, bh);
                mma16816(o[2 * ntp + 1], ah, bh + 2);
                mma16816(o[2 * ntp + 1], ah, bl + 2);
                mma16816(o[2 * ntp + 1], al, bh + 2);
            }
        }
    }

    // ---- epilogue: normalize + write y as single fp16 ----
    {
        float inv0 = 1.f / l_[0];
        float inv1 = 1.f / l_[1];
        int row0 = q0 + wid * 16 + g;
        size_t t0 = (size_t)b * SEQ + row0;
#pragma unroll
        for (int nt = 0; nt < 8; nt++) {
            int col = h * D_HEAD + nt * 8 + 2 * t;
            *(uint32_t*)&yf[t0 * D_MODEL + col] =
                pack_f16x2(o[nt][0] * inv0, o[nt][1] * inv0);
            *(uint32_t*)&yf[(t0 + 8) * D_MODEL + col] =
                pack_f16x2(o[nt][2] * inv1, o[nt][3] * inv1);
        }
    }
}

// ---------------------------------------------------------------------------
extern "C" void kernel_launch(void* const* d_in, const int* in_sizes, int n_in,
                              void* d_out, int out_size) {
    const float* x    = (const float*)d_in[0];
    const float* Wqkv = (const float*)d_in[1];
    const float* Wout = (const float*)d_in[2];
    float* out = (float*)d_out;

    float* qkv;
    cudaGetSymbolAddress((void**)&qkv, g_qkv);
    __half *xf, *w1h, *w1l, *w2h, *w2l, *yf;
    cudaGetSymbolAddress((void**)&xf, g_xf);
    cudaGetSymbolAddress((void**)&w1h, g_w1h);
    cudaGetSymbolAddress((void**)&w1l, g_w1l);
    cudaGetSymbolAddress((void**)&w2h, g_w2h);
    cudaGetSymbolAddress((void**)&w2l, g_w2l);
    cudaGetSymbolAddress((void**)&yf, g_yf);

    cudaFuncSetAttribute(gemm_f16, cudaFuncAttributeMaxDynamicSharedMemorySize, GEMM_SMEM);
    cudaFuncSetAttribute(attn_tc, cudaFuncAttributeMaxDynamicSharedMemorySize, AT_SMEM);

    // Converts / splits (weights x64; Wqkv Q-rows x8 = 64 * attention scale 1/8)
    {
        int n4 = ROWS * D_MODEL / 4;
        conv_f16<<<(n4 + 255) / 256, 256>>>(x, xf, n4);
        int w1n4 = 3 * D_MODEL * D_MODEL / 4;
        split_f16w<<<(w1n4 + 255) / 256, 256>>>(Wqkv, w1h, w1l, w1n4,
                                                D_MODEL * D_MODEL / 4);
        int w2n4 = D_MODEL * D_MODEL / 4;
        split_f16w<<<(w2n4 + 255) / 256, 256>>>(Wout, w2h, w2l, w2n4, 0);
    }

    // 1) QKV projection: [4096,1024] x [3072,1024]^T -> fp32 qkv (x 1/64)
    gemm_f16<<<dim3(3 * D_MODEL / 128, ROWS / 128), 256, GEMM_SMEM>>>(
        xf, w1h, w1l, qkv, ROWS, 3 * D_MODEL, D_MODEL);

    // 2) Tensor-core causal flash attention -> yf (fp16)
    attn_tc<<<dim3(SEQ / 128, NUM_HEADS, BATCH), 256, AT_SMEM>>>(qkv, yf);

    // 3) Output projection -> fp32 out (x 1/64)
    gemm_f16<<<dim3(D_MODEL / 128, ROWS / 128), 256, GEMM_SMEM>>>(
        yf, w2h, w2l, out, ROWS, D_MODEL, D_MODEL);
}

// round 8
// speedup vs baseline: 1.3736x; 1.1066x over previous
#include <cuda_runtime.h>
#include <cuda_fp16.h>
#include <cstdint>

#define D_MODEL   1024
#define NUM_HEADS 16
#define D_HEAD    64
#define BATCH     2
#define SEQ       2048
#define ROWS      (BATCH * SEQ)   // 4096

// ---------------------------------------------------------------------------
// Scratch (alloc-free rule: __device__ globals)
// ---------------------------------------------------------------------------
__device__ __half g_qkvh[(size_t)ROWS * 3 * D_MODEL];    // qkv fp16 hi
__device__ __half g_qkvl[(size_t)ROWS * 3 * D_MODEL];    // qkv fp16 residual lo
__device__ __half g_xf[(size_t)ROWS * D_MODEL];          // x as fp16
__device__ __half g_w1h[(size_t)3 * D_MODEL * D_MODEL];  // Wqkv hi (x64, Q rows x8)
__device__ __half g_w1l[(size_t)3 * D_MODEL * D_MODEL];  // Wqkv lo
__device__ __half g_w2h[(size_t)D_MODEL * D_MODEL];      // Wout hi (x64)
__device__ __half g_w2l[(size_t)D_MODEL * D_MODEL];      // Wout lo
__device__ __half g_yf[(size_t)ROWS * D_MODEL];          // attention out, fp16

// ---------------------------------------------------------------------------
__device__ __forceinline__ uint32_t smem_u32(const void* p) {
    uint32_t a;
    asm("{ .reg .u64 t; cvta.to.shared.u64 t, %1; cvt.u32.u64 %0, t; }"
        : "=r"(a) : "l"(p));
    return a;
}

__device__ __forceinline__ void cp_async16(uint32_t dst, const void* src) {
    asm volatile("cp.async.cg.shared.global [%0], [%1], 16;" :: "r"(dst), "l"(src));
}

// fp16 MMA
__device__ __forceinline__ void mma16816h(float* c, const uint32_t* a, const uint32_t* b) {
    asm volatile(
        "mma.sync.aligned.m16n8k16.row.col.f32.f16.f16.f32 "
        "{%0,%1,%2,%3}, {%4,%5,%6,%7}, {%8,%9}, {%0,%1,%2,%3};"
        : "+f"(c[0]), "+f"(c[1]), "+f"(c[2]), "+f"(c[3])
        : "r"(a[0]), "r"(a[1]), "r"(a[2]), "r"(a[3]), "r"(b[0]), "r"(b[1]));
}

__device__ __forceinline__ void ldsm_x4(uint32_t* r, uint32_t addr) {
    asm volatile("ldmatrix.sync.aligned.m8n8.x4.shared.b16 {%0,%1,%2,%3}, [%4];"
        : "=r"(r[0]), "=r"(r[1]), "=r"(r[2]), "=r"(r[3]) : "r"(addr));
}

__device__ __forceinline__ void ldsm_x4_t(uint32_t* r, uint32_t addr) {
    asm volatile("ldmatrix.sync.aligned.m8n8.x4.trans.shared.b16 {%0,%1,%2,%3}, [%4];"
        : "=r"(r[0]), "=r"(r[1]), "=r"(r[2]), "=r"(r[3]) : "r"(addr));
}

__device__ __forceinline__ uint32_t pack_f16x2(float x, float y) {
    uint32_t r;
    asm("cvt.rn.f16x2.f32 %0, %1, %2;" : "=r"(r) : "f"(y), "f"(x));
    return r;
}

// pack two fp32 -> fp16x2 hi word + fp16x2 residual lo word
__device__ __forceinline__ void pack_f16_hilo(float x, float y, uint32_t& hp, uint32_t& lp) {
    asm("cvt.rn.f16x2.f32 %0, %1, %2;" : "=r"(hp) : "f"(y), "f"(x));
    __half2 h2 = *reinterpret_cast<__half2*>(&hp);
    float2 f = __half22float2(h2);
    lp = pack_f16x2(x - f.x, y - f.y);
}

// ---------------------------------------------------------------------------
// fp32 -> fp16 single convert
// ---------------------------------------------------------------------------
__global__ __launch_bounds__(256) void conv_f16(const float* __restrict__ src,
                                                __half* __restrict__ dst, int n4) {
    int i = blockIdx.x * blockDim.x + threadIdx.x;
    if (i >= n4) return;
    float4 v = ((const float4*)src)[i];
    uint32_t p0 = pack_f16x2(v.x, v.y);
    uint32_t p1 = pack_f16x2(v.z, v.w);
    ((uint2*)dst)[i] = make_uint2(p0, p1);
}

// fp32 -> fp16 hi/lo split with per-region scale (Q rows x8, rest x64)
__global__ __launch_bounds__(256) void split_f16w(const float* __restrict__ src,
                                                  __half* __restrict__ hi,
                                                  __half* __restrict__ lo,
                                                  int n4, int q4_until) {
    int i = blockIdx.x * blockDim.x + threadIdx.x;
    if (i >= n4) return;
    float sc = (i < q4_until) ? 8.0f : 64.0f;
    float4 v = ((const float4*)src)[i];
    float f[4] = {v.x * sc, v.y * sc, v.z * sc, v.w * sc};
    __half h[4], l[4];
#pragma unroll
    for (int j = 0; j < 4; j++) {
        h[j] = __float2half_rn(f[j]);
        l[j] = __float2half_rn(f[j] - __half2float(h[j]));
    }
    ((uint2*)hi)[i] = *(uint2*)h;
    ((uint2*)lo)[i] = *(uint2*)l;
}

// ---------------------------------------------------------------------------
// fp16 2-term GEMM NT: C[m,n] = (1/64) * sum_k A[m,k]*(Bh[n,k]+Bl[n,k])
// Block 128x128, BK=32, 8 warps, 3-stage cp.async, 2 CTAs/SM.
// F16OUT: write fp16 hi/lo (feeds attention) instead of fp32.
// ---------------------------------------------------------------------------
#define SROW       40                    // fp16 elems per smem row (80 B)
#define TILE_B     (128 * SROW * 2)      // 10240 B per tile
#define STAGE_B    (3 * TILE_B)          // A, Bh, Bl = 30720 B
#define NSTAGE     3
#define GEMM_SMEM  (NSTAGE * STAGE_B)    // 92160 B

__device__ __forceinline__ void load_stage(uint32_t s_base,
                                           const __half* Af,
                                           const __half* Bh, const __half* Bl,
                                           int m0, int n0, int k0, int K, int tid) {
#pragma unroll
    for (int p = 0; p < 2; p++) {
        int v = tid + p * 256;
        int row = v >> 2;
        int c = v & 3;
        uint32_t soff = (uint32_t)(row * (SROW * 2) + c * 16);
        cp_async16(s_base + soff,
                   Af + (size_t)(m0 + row) * K + k0 + c * 8);
        cp_async16(s_base + TILE_B + soff,
                   Bh + (size_t)(n0 + row) * K + k0 + c * 8);
        cp_async16(s_base + 2 * TILE_B + soff,
                   Bl + (size_t)(n0 + row) * K + k0 + c * 8);
    }
}

template <bool F16OUT>
__global__ __launch_bounds__(256, 2) void gemm_f16(const __half* __restrict__ Af,
                                                   const __half* __restrict__ Bh,
                                                   const __half* __restrict__ Bl,
                                                   float* __restrict__ C,
                                                   __half* __restrict__ Ch,
                                                   __half* __restrict__ Cl,
                                                   int M, int N, int K) {
    extern __shared__ __half smem[];
    const uint32_t sbase = smem_u32(smem);

    const int tid = threadIdx.x;
    const int wid = tid >> 5;
    const int lane = tid & 31;
    const int g = lane >> 2;
    const int t = lane & 3;
    const int m0 = blockIdx.y * 128;
    const int n0 = blockIdx.x * 128;
    const int wm = (wid >> 2) * 64;
    const int wn = (wid & 3) * 32;

    const int lrow  = (lane & 7) + 8 * ((lane >> 3) & 1);   // A frag
    const int lcol8 = 8 * (lane >> 4);
    const int lrowK = (lane & 7) + 8 * (lane >> 4);          // B frag
    const int lcol8K = 8 * ((lane >> 3) & 1);

    float acc[4][4][4];
#pragma unroll
    for (int mi = 0; mi < 4; mi++)
#pragma unroll
        for (int ni = 0; ni < 4; ni++)
#pragma unroll
            for (int r = 0; r < 4; r++) acc[mi][ni][r] = 0.f;

    const int NIT = K / 32;

    load_stage(sbase, Af, Bh, Bl, m0, n0, 0, K, tid);
    asm volatile("cp.async.commit_group;" ::: "memory");
    load_stage(sbase + STAGE_B, Af, Bh, Bl, m0, n0, 32, K, tid);
    asm volatile("cp.async.commit_group;" ::: "memory");

    for (int it = 0; it < NIT; it++) {
        if (it + 2 < NIT) {
            load_stage(sbase + ((it + 2) % NSTAGE) * STAGE_B, Af, Bh, Bl,
                       m0, n0, (it + 2) * 32, K, tid);
        }
        asm volatile("cp.async.commit_group;" ::: "memory");
        asm volatile("cp.async.wait_group 2;" ::: "memory");
        __syncthreads();

        const uint32_t sA  = sbase + (it % NSTAGE) * STAGE_B;
        const uint32_t sBh = sA + TILE_B;
        const uint32_t sBl = sA + 2 * TILE_B;

#pragma unroll
        for (int ks = 0; ks < 2; ks++) {
            const int kb = ks * 16;
            uint32_t bh[2][4], bl[2][4];
#pragma unroll
            for (int np = 0; np < 2; np++) {
                uint32_t boff = (uint32_t)((wn + np * 16 + lrowK) * (SROW * 2)
                                           + (kb + lcol8K) * 2);
                ldsm_x4(bh[np], sBh + boff);
                ldsm_x4(bl[np], sBl + boff);
            }
#pragma unroll
            for (int mi = 0; mi < 4; mi++) {
                uint32_t ah[4];
                uint32_t aoff = (uint32_t)((wm + mi * 16 + lrow) * (SROW * 2)
                                           + (kb + lcol8) * 2);
                ldsm_x4(ah, sA + aoff);
#pragma unroll
                for (int np = 0; np < 2; np++) {
                    mma16816h(acc[mi][2 * np],     ah, bh[np]);
                    mma16816h(acc[mi][2 * np],     ah, bl[np]);
                    mma16816h(acc[mi][2 * np + 1], ah, bh[np] + 2);
                    mma16816h(acc[mi][2 * np + 1], ah, bl[np] + 2);
                }
            }
        }
        __syncthreads();
    }

    const float cs = 1.0f / 64.0f;
#pragma unroll
    for (int mi = 0; mi < 4; mi++) {
        int row0 = m0 + wm + mi * 16 + g;
#pragma unroll
        for (int ni = 0; ni < 4; ni++) {
            int col = n0 + wn + ni * 8 + 2 * t;
            if (F16OUT) {
                uint32_t hp, lp;
                pack_f16_hilo(acc[mi][ni][0] * cs, acc[mi][ni][1] * cs, hp, lp);
                *(uint32_t*)&Ch[(size_t)row0 * N + col] = hp;
                *(uint32_t*)&Cl[(size_t)row0 * N + col] = lp;
                pack_f16_hilo(acc[mi][ni][2] * cs, acc[mi][ni][3] * cs, hp, lp);
                *(uint32_t*)&Ch[(size_t)(row0 + 8) * N + col] = hp;
                *(uint32_t*)&Cl[(size_t)(row0 + 8) * N + col] = lp;
            } else {
                *(float2*)&C[(size_t)row0 * N + col] =
                    make_float2(acc[mi][ni][0] * cs, acc[mi][ni][1] * cs);
                *(float2*)&C[(size_t)(row0 + 8) * N + col] =
                    make_float2(acc[mi][ni][2] * cs, acc[mi][ni][3] * cs);
            }
        }
    }
}

// ---------------------------------------------------------------------------
// fp16 tensor-core causal flash attention. BQ=128, BK=64, Dh=64, 256 threads.
// qkv arrives pre-split fp16 hi/lo. S = Qh*(Kh+Kl); O += f16(P)*(Vh+Vl).
// K/V tiles double-buffered via cp.async. Q pre-scaled via Wqkv.
// smem: QH 18432 | 2 stages x (KH,KL,VH,VL 9216 each) = 92160 B
// ---------------------------------------------------------------------------
#define AT_STAGE 36864
#define AT_SMEM  (18432 + 2 * AT_STAGE)   // 92160

__device__ __forceinline__ void load_kv(uint32_t stage_base,
                                        const __half* kh, const __half* kl,
                                        const __half* vh, const __half* vl,
                                        int k0, int tid) {
#pragma unroll
    for (int p = 0; p < 2; p++) {
        int v = tid + p * 256;        // 0..511
        int row = v >> 3, c = v & 7;
        size_t go = (size_t)(k0 + row) * (3 * D_MODEL) + c * 8;
        uint32_t soff = (uint32_t)(row * 144 + c * 16);
        cp_async16(stage_base + soff,             kh + go);
        cp_async16(stage_base + 9216 + soff,      kl + go);
        cp_async16(stage_base + 18432 + soff,     vh + go);
        cp_async16(stage_base + 27648 + soff,     vl + go);
    }
}

__global__ __launch_bounds__(256, 2) void attn_tc(const __half* __restrict__ qkvh,
                                                  const __half* __restrict__ qkvl,
                                                  __half* __restrict__ yf) {
    extern __shared__ __half asmem[];
    const uint32_t sb = smem_u32(asmem);
    const uint32_t QH = sb;
    const uint32_t ST0 = sb + 18432;

    const int tid = threadIdx.x;
    const int wid = tid >> 5;
    const int lane = tid & 31;
    const int g = lane >> 2, t = lane & 3;
    const int qt = blockIdx.x, h = blockIdx.y, b = blockIdx.z;
    const int q0 = qt * 128;

    const size_t rowstride = 3 * D_MODEL;
    const __half* qh = qkvh + (size_t)b * SEQ * rowstride + h * D_HEAD;
    const __half* kh = qh + D_MODEL;
    const __half* vh = qh + 2 * D_MODEL;
    const __half* kl = qkvl + (size_t)b * SEQ * rowstride + h * D_HEAD + D_MODEL;
    const __half* vl = kl + D_MODEL;

    const int lrow  = (lane & 7) + 8 * ((lane >> 3) & 1);   // A frag / V trans
    const int lcol8 = 8 * (lane >> 4);
    const int lrowK = (lane & 7) + 8 * (lane >> 4);          // K B-frag
    const int lcol8K = 8 * ((lane >> 3) & 1);

    // ---- async-load Q hi tile (128 x 64 fp16) ----
#pragma unroll
    for (int p = 0; p < 4; p++) {
        int v = tid + p * 256;        // 0..1023
        int row = v >> 3, c = v & 7;
        cp_async16(QH + row * 144 + c * 16,
                   qh + (size_t)(q0 + row) * rowstride + c * 8);
    }
    asm volatile("cp.async.commit_group;" ::: "memory");

    // ---- prologue: KV tile 0 ----
    load_kv(ST0, kh, kl, vh, vl, 0, tid);
    asm volatile("cp.async.commit_group;" ::: "memory");

    float m_[2] = {-1e30f, -1e30f};
    float l_[2] = {0.f, 0.f};
    float o[8][4];
#pragma unroll
    for (int nt = 0; nt < 8; nt++)
#pragma unroll
        for (int c = 0; c < 4; c++) o[nt][c] = 0.f;

    const int ntiles = 2 * qt + 2;
    for (int kt = 0; kt < ntiles; kt++) {
        const uint32_t CUR = ST0 + (kt & 1) * AT_STAGE;
        if (kt + 1 < ntiles) {
            load_kv(ST0 + ((kt + 1) & 1) * AT_STAGE, kh, kl, vh, vl,
                    (kt + 1) * 64, tid);
            asm volatile("cp.async.commit_group;" ::: "memory");
            asm volatile("cp.async.wait_group 1;" ::: "memory");
        } else {
            asm volatile("cp.async.wait_group 0;" ::: "memory");
        }
        __syncthreads();

        const uint32_t KHs = CUR, KLs = CUR + 9216, VHs = CUR + 18432, VLs = CUR + 27648;

        // ---- S = Qh (Kh + Kl)^T ----
        float s[8][4];
#pragma unroll
        for (int nt = 0; nt < 8; nt++)
#pragma unroll
            for (int c = 0; c < 4; c++) s[nt][c] = 0.f;

#pragma unroll
        for (int ks = 0; ks < 4; ks++) {
            uint32_t a[4];
            uint32_t qoff = (uint32_t)((wid * 16 + lrow) * 144 + (ks * 16 + lcol8) * 2);
            ldsm_x4(a, QH + qoff);
#pragma unroll
            for (int ntp = 0; ntp < 4; ntp++) {
                uint32_t bh[4], bl[4];
                uint32_t koff = (uint32_t)((ntp * 16 + lrowK) * 144 + (ks * 16 + lcol8K) * 2);
                ldsm_x4(bh, KHs + koff);
                ldsm_x4(bl, KLs + koff);
                mma16816h(s[2 * ntp],     a, bh);
                mma16816h(s[2 * ntp],     a, bl);
                mma16816h(s[2 * ntp + 1], a, bh + 2);
                mma16816h(s[2 * ntp + 1], a, bl + 2);
            }
        }

        // ---- causal mask ----
        if (kt >= 2 * qt) {
#pragma unroll
            for (int nt = 0; nt < 8; nt++)
#pragma unroll
                for (int c = 0; c < 4; c++) {
                    int row = q0 + wid * 16 + g + (c >> 1) * 8;
                    int col = kt * 64 + nt * 8 + 2 * t + (c & 1);
                    if (col > row) s[nt][c] = -1e30f;
                }
        }

        // ---- online softmax ----
#pragma unroll
        for (int r = 0; r < 2; r++) {
            float mx = -1e30f;
#pragma unroll
            for (int nt = 0; nt < 8; nt++)
                mx = fmaxf(mx, fmaxf(s[nt][2 * r], s[nt][2 * r + 1]));
            mx = fmaxf(mx, __shfl_xor_sync(0xffffffffu, mx, 1));
            mx = fmaxf(mx, __shfl_xor_sync(0xffffffffu, mx, 2));
            float mnew = fmaxf(m_[r], mx);
            float corr = __expf(m_[r] - mnew);
            m_[r] = mnew;
            float ls = 0.f;
#pragma unroll
            for (int nt = 0; nt < 8; nt++) {
                float p0 = __expf(s[nt][2 * r] - mnew);
                float p1 = __expf(s[nt][2 * r + 1] - mnew);
                s[nt][2 * r] = p0;
                s[nt][2 * r + 1] = p1;
                ls += p0 + p1;
            }
            ls += __shfl_xor_sync(0xffffffffu, ls, 1);
            ls += __shfl_xor_sync(0xffffffffu, ls, 2);
            l_[r] = l_[r] * corr + ls;
#pragma unroll
            for (int nt = 0; nt < 8; nt++) {
                o[nt][2 * r] *= corr;
                o[nt][2 * r + 1] *= corr;
            }
        }

        // ---- O += f16(P) (Vh + Vl) ----
#pragma unroll
        for (int kc = 0; kc < 4; kc++) {
            uint32_t pa[4];
            pa[0] = pack_f16x2(s[2 * kc][0],     s[2 * kc][1]);
            pa[1] = pack_f16x2(s[2 * kc][2],     s[2 * kc][3]);
            pa[2] = pack_f16x2(s[2 * kc + 1][0], s[2 * kc + 1][1]);
            pa[3] = pack_f16x2(s[2 * kc + 1][2], s[2 * kc + 1][3]);
#pragma unroll
            for (int ntp = 0; ntp < 4; ntp++) {
                uint32_t bh[4], bl[4];
                uint32_t voff = (uint32_t)((kc * 16 + lrow) * 144 + (ntp * 16 + lcol8) * 2);
                ldsm_x4_t(bh, VHs + voff);
                ldsm_x4_t(bl, VLs + voff);
                mma16816h(o[2 * ntp],     pa, bh);
                mma16816h(o[2 * ntp],     pa, bl);
                mma16816h(o[2 * ntp + 1], pa, bh + 2);
                mma16816h(o[2 * ntp + 1], pa, bl + 2);
            }
        }
        __syncthreads();   // all reads of CUR stage done before it is reloaded
    }

    // ---- epilogue: normalize + write y as fp16 ----
    {
        float inv0 = 1.f / l_[0];
        float inv1 = 1.f / l_[1];
        int row0 = q0 + wid * 16 + g;
        size_t t0 = (size_t)b * SEQ + row0;
#pragma unroll
        for (int nt = 0; nt < 8; nt++) {
            int col = h * D_HEAD + nt * 8 + 2 * t;
            *(uint32_t*)&yf[t0 * D_MODEL + col] =
                pack_f16x2(o[nt][0] * inv0, o[nt][1] * inv0);
            *(uint32_t*)&yf[(t0 + 8) * D_MODEL + col] =
                pack_f16x2(o[nt][2] * inv1, o[nt][3] * inv1);
        }
    }
}

// ---------------------------------------------------------------------------
extern "C" void kernel_launch(void* const* d_in, const int* in_sizes, int n_in,
                              void* d_out, int out_size) {
    const float* x    = (const float*)d_in[0];
    const float* Wqkv = (const float*)d_in[1];
    const float* Wout = (const float*)d_in[2];
    float* out = (float*)d_out;

    __half *qkvh, *qkvl, *xf, *w1h, *w1l, *w2h, *w2l, *yf;
    cudaGetSymbolAddress((void**)&qkvh, g_qkvh);
    cudaGetSymbolAddress((void**)&qkvl, g_qkvl);
    cudaGetSymbolAddress((void**)&xf, g_xf);
    cudaGetSymbolAddress((void**)&w1h, g_w1h);
    cudaGetSymbolAddress((void**)&w1l, g_w1l);
    cudaGetSymbolAddress((void**)&w2h, g_w2h);
    cudaGetSymbolAddress((void**)&w2l, g_w2l);
    cudaGetSymbolAddress((void**)&yf, g_yf);

    cudaFuncSetAttribute(gemm_f16<true>, cudaFuncAttributeMaxDynamicSharedMemorySize, GEMM_SMEM);
    cudaFuncSetAttribute(gemm_f16<false>, cudaFuncAttributeMaxDynamicSharedMemorySize, GEMM_SMEM);
    cudaFuncSetAttribute(attn_tc, cudaFuncAttributeMaxDynamicSharedMemorySize, AT_SMEM);

    // Converts / splits (weights x64; Wqkv Q-rows x8 = 64 * attention scale 1/8)
    {
        int n4 = ROWS * D_MODEL / 4;
        conv_f16<<<(n4 + 255) / 256, 256>>>(x, xf, n4);
        int w1n4 = 3 * D_MODEL * D_MODEL / 4;
        split_f16w<<<(w1n4 + 255) / 256, 256>>>(Wqkv, w1h, w1l, w1n4,
                                                D_MODEL * D_MODEL / 4);
        int w2n4 = D_MODEL * D_MODEL / 4;
        split_f16w<<<(w2n4 + 255) / 256, 256>>>(Wout, w2h, w2l, w2n4, 0);
    }

    // 1) QKV projection -> fp16 hi/lo qkv (x 1/64 folded)
    gemm_f16<true><<<dim3(3 * D_MODEL / 128, ROWS / 128), 256, GEMM_SMEM>>>(
        xf, w1h, w1l, nullptr, qkvh, qkvl, ROWS, 3 * D_MODEL, D_MODEL);

    // 2) fp16 tensor-core causal flash attention -> yf
    attn_tc<<<dim3(SEQ / 128, NUM_HEADS, BATCH), 256, AT_SMEM>>>(qkvh, qkvl, yf);

    // 3) Output projection -> fp32 out (x 1/64)
    gemm_f16<false><<<dim3(D_MODEL / 128, ROWS / 128), 256, GEMM_SMEM>>>(
        yf, w2h, w2l, out, nullptr, nullptr, ROWS, D_MODEL, D_MODEL);
}

// round 9
// speedup vs baseline: 1.7957x; 1.3073x over previous
#include <cuda_runtime.h>
#include <cuda_fp16.h>
#include <cstdint>

#define D_MODEL   1024
#define NUM_HEADS 16
#define D_HEAD    64
#define BATCH     2
#define SEQ       2048
#define ROWS      (BATCH * SEQ)   // 4096

// ---------------------------------------------------------------------------
// Scratch (alloc-free rule: __device__ globals)
// ---------------------------------------------------------------------------
__device__ __half g_qkvh[(size_t)ROWS * 3 * D_MODEL];    // qkv fp16 hi
__device__ __half g_qkvl[(size_t)ROWS * 3 * D_MODEL];    // qkv fp16 residual lo
__device__ __half g_xf[(size_t)ROWS * D_MODEL];          // x as fp16
__device__ __half g_w1f[(size_t)3 * D_MODEL * D_MODEL];  // Wqkv fp16 (Q rows /8)
__device__ __half g_w2f[(size_t)D_MODEL * D_MODEL];      // Wout fp16
__device__ __half g_yf[(size_t)ROWS * D_MODEL];          // attention out, fp16

// ---------------------------------------------------------------------------
__device__ __forceinline__ uint32_t smem_u32(const void* p) {
    uint32_t a;
    asm("{ .reg .u64 t; cvta.to.shared.u64 t, %1; cvt.u32.u64 %0, t; }"
        : "=r"(a) : "l"(p));
    return a;
}

__device__ __forceinline__ void cp_async16(uint32_t dst, const void* src) {
    asm volatile("cp.async.cg.shared.global [%0], [%1], 16;" :: "r"(dst), "l"(src));
}

// fp16 MMA
__device__ __forceinline__ void mma16816h(float* c, const uint32_t* a, const uint32_t* b) {
    asm volatile(
        "mma.sync.aligned.m16n8k16.row.col.f32.f16.f16.f32 "
        "{%0,%1,%2,%3}, {%4,%5,%6,%7}, {%8,%9}, {%0,%1,%2,%3};"
        : "+f"(c[0]), "+f"(c[1]), "+f"(c[2]), "+f"(c[3])
        : "r"(a[0]), "r"(a[1]), "r"(a[2]), "r"(a[3]), "r"(b[0]), "r"(b[1]));
}

__device__ __forceinline__ void ldsm_x4(uint32_t* r, uint32_t addr) {
    asm volatile("ldmatrix.sync.aligned.m8n8.x4.shared.b16 {%0,%1,%2,%3}, [%4];"
        : "=r"(r[0]), "=r"(r[1]), "=r"(r[2]), "=r"(r[3]) : "r"(addr));
}

__device__ __forceinline__ void ldsm_x4_t(uint32_t* r, uint32_t addr) {
    asm volatile("ldmatrix.sync.aligned.m8n8.x4.trans.shared.b16 {%0,%1,%2,%3}, [%4];"
        : "=r"(r[0]), "=r"(r[1]), "=r"(r[2]), "=r"(r[3]) : "r"(addr));
}

__device__ __forceinline__ uint32_t pack_f16x2(float x, float y) {
    uint32_t r;
    asm("cvt.rn.f16x2.f32 %0, %1, %2;" : "=r"(r) : "f"(y), "f"(x));
    return r;
}

// pack two fp32 -> fp16x2 hi word + fp16x2 residual lo word
__device__ __forceinline__ void pack_f16_hilo(float x, float y, uint32_t& hp, uint32_t& lp) {
    asm("cvt.rn.f16x2.f32 %0, %1, %2;" : "=r"(hp) : "f"(y), "f"(x));
    __half2 h2 = *reinterpret_cast<__half2*>(&hp);
    float2 f = __half22float2(h2);
    lp = pack_f16x2(x - f.x, y - f.y);
}

// ---------------------------------------------------------------------------
// fp32 -> fp16 convert; first scale4_until float4s scaled by `sc` (else 1.0)
// ---------------------------------------------------------------------------
__global__ __launch_bounds__(256) void conv_f16(const float* __restrict__ src,
                                                __half* __restrict__ dst,
                                                int n4, int scale4_until, float sc) {
    int i = blockIdx.x * blockDim.x + threadIdx.x;
    if (i >= n4) return;
    float s = (i < scale4_until) ? sc : 1.0f;
    float4 v = ((const float4*)src)[i];
    uint32_t p0 = pack_f16x2(v.x * s, v.y * s);
    uint32_t p1 = pack_f16x2(v.z * s, v.w * s);
    ((uint2*)dst)[i] = make_uint2(p0, p1);
}

// ---------------------------------------------------------------------------
// fp16 single-term GEMM NT: C[m,n] = sum_k A[m,k]*B[n,k]
// Block 128x128, BK=32, 8 warps (warp 64x32), 4-stage cp.async, 2 CTAs/SM.
// F16OUT: write fp16 hi/lo (feeds attention) instead of fp32.
// ---------------------------------------------------------------------------
#define SROW       40                    // fp16 elems per smem row (80 B)
#define TILE_B     (128 * SROW * 2)      // 10240 B per tile
#define STAGE_B    (2 * TILE_B)          // A, B = 20480 B
#define NSTAGE     4
#define GEMM_SMEM  (NSTAGE * STAGE_B)    // 81920 B

__device__ __forceinline__ void load_stage(uint32_t s_base,
                                           const __half* Af, const __half* Bf,
                                           int m0, int n0, int k0, int K, int tid) {
#pragma unroll
    for (int p = 0; p < 2; p++) {
        int v = tid + p * 256;
        int row = v >> 2;
        int c = v & 3;
        uint32_t soff = (uint32_t)(row * (SROW * 2) + c * 16);
        cp_async16(s_base + soff,
                   Af + (size_t)(m0 + row) * K + k0 + c * 8);
        cp_async16(s_base + TILE_B + soff,
                   Bf + (size_t)(n0 + row) * K + k0 + c * 8);
    }
}

template <bool F16OUT>
__global__ __launch_bounds__(256, 2) void gemm_f16(const __half* __restrict__ Af,
                                                   const __half* __restrict__ Bf,
                                                   float* __restrict__ C,
                                                   __half* __restrict__ Ch,
                                                   __half* __restrict__ Cl,
                                                   int M, int N, int K) {
    extern __shared__ __half smem[];
    const uint32_t sbase = smem_u32(smem);

    const int tid = threadIdx.x;
    const int wid = tid >> 5;
    const int lane = tid & 31;
    const int g = lane >> 2;
    const int t = lane & 3;
    const int m0 = blockIdx.y * 128;
    const int n0 = blockIdx.x * 128;
    const int wm = (wid >> 2) * 64;
    const int wn = (wid & 3) * 32;

    const int lrow  = (lane & 7) + 8 * ((lane >> 3) & 1);   // A frag
    const int lcol8 = 8 * (lane >> 4);
    const int lrowK = (lane & 7) + 8 * (lane >> 4);          // B frag
    const int lcol8K = 8 * ((lane >> 3) & 1);

    float acc[4][4][4];
#pragma unroll
    for (int mi = 0; mi < 4; mi++)
#pragma unroll
        for (int ni = 0; ni < 4; ni++)
#pragma unroll
            for (int r = 0; r < 4; r++) acc[mi][ni][r] = 0.f;

    const int NIT = K / 32;

    // Prologue: stages 0..2
#pragma unroll
    for (int s = 0; s < NSTAGE - 1; s++) {
        load_stage(sbase + s * STAGE_B, Af, Bf, m0, n0, s * 32, K, tid);
        asm volatile("cp.async.commit_group;" ::: "memory");
    }

    for (int it = 0; it < NIT; it++) {
        if (it + NSTAGE - 1 < NIT) {
            load_stage(sbase + ((it + NSTAGE - 1) % NSTAGE) * STAGE_B, Af, Bf,
                       m0, n0, (it + NSTAGE - 1) * 32, K, tid);
        }
        asm volatile("cp.async.commit_group;" ::: "memory");
        asm volatile("cp.async.wait_group %0;" :: "n"(NSTAGE - 1) : "memory");
        __syncthreads();

        const uint32_t sA = sbase + (it % NSTAGE) * STAGE_B;
        const uint32_t sB = sA + TILE_B;

#pragma unroll
        for (int ks = 0; ks < 2; ks++) {
            const int kb = ks * 16;
            uint32_t b[2][4];
#pragma unroll
            for (int np = 0; np < 2; np++) {
                uint32_t boff = (uint32_t)((wn + np * 16 + lrowK) * (SROW * 2)
                                           + (kb + lcol8K) * 2);
                ldsm_x4(b[np], sB + boff);
            }
#pragma unroll
            for (int mi = 0; mi < 4; mi++) {
                uint32_t a[4];
                uint32_t aoff = (uint32_t)((wm + mi * 16 + lrow) * (SROW * 2)
                                           + (kb + lcol8) * 2);
                ldsm_x4(a, sA + aoff);
#pragma unroll
                for (int np = 0; np < 2; np++) {
                    mma16816h(acc[mi][2 * np],     a, b[np]);
                    mma16816h(acc[mi][2 * np + 1], a, b[np] + 2);
                }
            }
        }
        __syncthreads();
    }

#pragma unroll
    for (int mi = 0; mi < 4; mi++) {
        int row0 = m0 + wm + mi * 16 + g;
#pragma unroll
        for (int ni = 0; ni < 4; ni++) {
            int col = n0 + wn + ni * 8 + 2 * t;
            if (F16OUT) {
                uint32_t hp, lp;
                pack_f16_hilo(acc[mi][ni][0], acc[mi][ni][1], hp, lp);
                *(uint32_t*)&Ch[(size_t)row0 * N + col] = hp;
                *(uint32_t*)&Cl[(size_t)row0 * N + col] = lp;
                pack_f16_hilo(acc[mi][ni][2], acc[mi][ni][3], hp, lp);
                *(uint32_t*)&Ch[(size_t)(row0 + 8) * N + col] = hp;
                *(uint32_t*)&Cl[(size_t)(row0 + 8) * N + col] = lp;
            } else {
                *(float2*)&C[(size_t)row0 * N + col] =
                    make_float2(acc[mi][ni][0], acc[mi][ni][1]);
                *(float2*)&C[(size_t)(row0 + 8) * N + col] =
                    make_float2(acc[mi][ni][2], acc[mi][ni][3]);
            }
        }
    }
}

// ---------------------------------------------------------------------------
// fp16 tensor-core causal flash attention (unchanged from R8 — proven).
// BQ=128, BK=64, Dh=64, 256 threads. qkv pre-split fp16 hi/lo.
// S = Qh*(Kh+Kl); O += f16(P)*(Vh+Vl). K/V double-buffered cp.async.
// ---------------------------------------------------------------------------
#define AT_STAGE 36864
#define AT_SMEM  (18432 + 2 * AT_STAGE)   // 92160

__device__ __forceinline__ void load_kv(uint32_t stage_base,
                                        const __half* kh, const __half* kl,
                                        const __half* vh, const __half* vl,
                                        int k0, int tid) {
#pragma unroll
    for (int p = 0; p < 2; p++) {
        int v = tid + p * 256;        // 0..511
        int row = v >> 3, c = v & 7;
        size_t go = (size_t)(k0 + row) * (3 * D_MODEL) + c * 8;
        uint32_t soff = (uint32_t)(row * 144 + c * 16);
        cp_async16(stage_base + soff,             kh + go);
        cp_async16(stage_base + 9216 + soff,      kl + go);
        cp_async16(stage_base + 18432 + soff,     vh + go);
        cp_async16(stage_base + 27648 + soff,     vl + go);
    }
}

__global__ __launch_bounds__(256, 2) void attn_tc(const __half* __restrict__ qkvh,
                                                  const __half* __restrict__ qkvl,
                                                  __half* __restrict__ yf) {
    extern __shared__ __half asmem[];
    const uint32_t sb = smem_u32(asmem);
    const uint32_t QH = sb;
    const uint32_t ST0 = sb + 18432;

    const int tid = threadIdx.x;
    const int wid = tid >> 5;
    const int lane = tid & 31;
    const int g = lane >> 2, t = lane & 3;
    const int qt = blockIdx.x, h = blockIdx.y, b = blockIdx.z;
    const int q0 = qt * 128;

    const size_t rowstride = 3 * D_MODEL;
    const __half* qh = qkvh + (size_t)b * SEQ * rowstride + h * D_HEAD;
    const __half* kh = qh + D_MODEL;
    const __half* vh = qh + 2 * D_MODEL;
    const __half* kl = qkvl + (size_t)b * SEQ * rowstride + h * D_HEAD + D_MODEL;
    const __half* vl = kl + D_MODEL;

    const int lrow  = (lane & 7) + 8 * ((lane >> 3) & 1);
    const int lcol8 = 8 * (lane >> 4);
    const int lrowK = (lane & 7) + 8 * (lane >> 4);
    const int lcol8K = 8 * ((lane >> 3) & 1);

    // ---- async-load Q hi tile ----
#pragma unroll
    for (int p = 0; p < 4; p++) {
        int v = tid + p * 256;
        int row = v >> 3, c = v & 7;
        cp_async16(QH + row * 144 + c * 16,
                   qh + (size_t)(q0 + row) * rowstride + c * 8);
    }
    asm volatile("cp.async.commit_group;" ::: "memory");

    load_kv(ST0, kh, kl, vh, vl, 0, tid);
    asm volatile("cp.async.commit_group;" ::: "memory");

    float m_[2] = {-1e30f, -1e30f};
    float l_[2] = {0.f, 0.f};
    float o[8][4];
#pragma unroll
    for (int nt = 0; nt < 8; nt++)
#pragma unroll
        for (int c = 0; c < 4; c++) o[nt][c] = 0.f;

    const int ntiles = 2 * qt + 2;
    for (int kt = 0; kt < ntiles; kt++) {
        const uint32_t CUR = ST0 + (kt & 1) * AT_STAGE;
        if (kt + 1 < ntiles) {
            load_kv(ST0 + ((kt + 1) & 1) * AT_STAGE, kh, kl, vh, vl,
                    (kt + 1) * 64, tid);
            asm volatile("cp.async.commit_group;" ::: "memory");
            asm volatile("cp.async.wait_group 1;" ::: "memory");
        } else {
            asm volatile("cp.async.wait_group 0;" ::: "memory");
        }
        __syncthreads();

        const uint32_t KHs = CUR, KLs = CUR + 9216, VHs = CUR + 18432, VLs = CUR + 27648;

        float s[8][4];
#pragma unroll
        for (int nt = 0; nt < 8; nt++)
#pragma unroll
            for (int c = 0; c < 4; c++) s[nt][c] = 0.f;

#pragma unroll
        for (int ks = 0; ks < 4; ks++) {
            uint32_t a[4];
            uint32_t qoff = (uint32_t)((wid * 16 + lrow) * 144 + (ks * 16 + lcol8) * 2);
            ldsm_x4(a, QH + qoff);
#pragma unroll
            for (int ntp = 0; ntp < 4; ntp++) {
                uint32_t bh[4], bl[4];
                uint32_t koff = (uint32_t)((ntp * 16 + lrowK) * 144 + (ks * 16 + lcol8K) * 2);
                ldsm_x4(bh, KHs + koff);
                ldsm_x4(bl, KLs + koff);
                mma16816h(s[2 * ntp],     a, bh);
                mma16816h(s[2 * ntp],     a, bl);
                mma16816h(s[2 * ntp + 1], a, bh + 2);
                mma16816h(s[2 * ntp + 1], a, bl + 2);
            }
        }

        if (kt >= 2 * qt) {
#pragma unroll
            for (int nt = 0; nt < 8; nt++)
#pragma unroll
                for (int c = 0; c < 4; c++) {
                    int row = q0 + wid * 16 + g + (c >> 1) * 8;
                    int col = kt * 64 + nt * 8 + 2 * t + (c & 1);
                    if (col > row) s[nt][c] = -1e30f;
                }
        }

#pragma unroll
        for (int r = 0; r < 2; r++) {
            float mx = -1e30f;
#pragma unroll
            for (int nt = 0; nt < 8; nt++)
                mx = fmaxf(mx, fmaxf(s[nt][2 * r], s[nt][2 * r + 1]));
            mx = fmaxf(mx, __shfl_xor_sync(0xffffffffu, mx, 1));
            mx = fmaxf(mx, __shfl_xor_sync(0xffffffffu, mx, 2));
            float mnew = fmaxf(m_[r], mx);
            float corr = __expf(m_[r] - mnew);
            m_[r] = mnew;
            float ls = 0.f;
#pragma unroll
            for (int nt = 0; nt < 8; nt++) {
                float p0 = __expf(s[nt][2 * r] - mnew);
                float p1 = __expf(s[nt][2 * r + 1] - mnew);
                s[nt][2 * r] = p0;
                s[nt][2 * r + 1] = p1;
                ls += p0 + p1;
            }
            ls += __shfl_xor_sync(0xffffffffu, ls, 1);
            ls += __shfl_xor_sync(0xffffffffu, ls, 2);
            l_[r] = l_[r] * corr + ls;
#pragma unroll
            for (int nt = 0; nt < 8; nt++) {
                o[nt][2 * r] *= corr;
                o[nt][2 * r + 1] *= corr;
            }
        }

#pragma unroll
        for (int kc = 0; kc < 4; kc++) {
            uint32_t pa[4];
            pa[0] = pack_f16x2(s[2 * kc][0],     s[2 * kc][1]);
            pa[1] = pack_f16x2(s[2 * kc][2],     s[2 * kc][3]);
            pa[2] = pack_f16x2(s[2 * kc + 1][0], s[2 * kc + 1][1]);
            pa[3] = pack_f16x2(s[2 * kc + 1][2], s[2 * kc + 1][3]);
#pragma unroll
            for (int ntp = 0; ntp < 4; ntp++) {
                uint32_t bh[4], bl[4];
                uint32_t voff = (uint32_t)((kc * 16 + lrow) * 144 + (ntp * 16 + lcol8) * 2);
                ldsm_x4_t(bh, VHs + voff);
                ldsm_x4_t(bl, VLs + voff);
                mma16816h(o[2 * ntp],     pa, bh);
                mma16816h(o[2 * ntp],     pa, bl);
                mma16816h(o[2 * ntp + 1], pa, bh + 2);
                mma16816h(o[2 * ntp + 1], pa, bl + 2);
            }
        }
        __syncthreads();
    }

    {
        float inv0 = 1.f / l_[0];
        float inv1 = 1.f / l_[1];
        int row0 = q0 + wid * 16 + g;
        size_t t0 = (size_t)b * SEQ + row0;
#pragma unroll
        for (int nt = 0; nt < 8; nt++) {
            int col = h * D_HEAD + nt * 8 + 2 * t;
            *(uint32_t*)&yf[t0 * D_MODEL + col] =
                pack_f16x2(o[nt][0] * inv0, o[nt][1] * inv0);
            *(uint32_t*)&yf[(t0 + 8) * D_MODEL + col] =
                pack_f16x2(o[nt][2] * inv1, o[nt][3] * inv1);
        }
    }
}

// ---------------------------------------------------------------------------
extern "C" void kernel_launch(void* const* d_in, const int* in_sizes, int n_in,
                              void* d_out, int out_size) {
    const float* x    = (const float*)d_in[0];
    const float* Wqkv = (const float*)d_in[1];
    const float* Wout = (const float*)d_in[2];
    float* out = (float*)d_out;

    __half *qkvh, *qkvl, *xf, *w1f, *w2f, *yf;
    cudaGetSymbolAddress((void**)&qkvh, g_qkvh);
    cudaGetSymbolAddress((void**)&qkvl, g_qkvl);
    cudaGetSymbolAddress((void**)&xf, g_xf);
    cudaGetSymbolAddress((void**)&w1f, g_w1f);
    cudaGetSymbolAddress((void**)&w2f, g_w2f);
    cudaGetSymbolAddress((void**)&yf, g_yf);

    cudaFuncSetAttribute(gemm_f16<true>, cudaFuncAttributeMaxDynamicSharedMemorySize, GEMM_SMEM);
    cudaFuncSetAttribute(gemm_f16<false>, cudaFuncAttributeMaxDynamicSharedMemorySize, GEMM_SMEM);
    cudaFuncSetAttribute(attn_tc, cudaFuncAttributeMaxDynamicSharedMemorySize, AT_SMEM);

    // Converts (Wqkv Q-rows pre-scaled by 1/8 = attention scale, exact)
    {
        int n4 = ROWS * D_MODEL / 4;
        conv_f16<<<(n4 + 255) / 256, 256>>>(x, xf, n4, 0, 1.0f);
        int w1n4 = 3 * D_MODEL * D_MODEL / 4;
        conv_f16<<<(w1n4 + 255) / 256, 256>>>(Wqkv, w1f, w1n4,
                                              D_MODEL * D_MODEL / 4, 0.125f);
        int w2n4 = D_MODEL * D_MODEL / 4;
        conv_f16<<<(w2n4 + 255) / 256, 256>>>(Wout, w2f, w2n4, 0, 1.0f);
    }

    // 1) QKV projection -> fp16 hi/lo qkv
    gemm_f16<true><<<dim3(3 * D_MODEL / 128, ROWS / 128), 256, GEMM_SMEM>>>(
        xf, w1f, nullptr, qkvh, qkvl, ROWS, 3 * D_MODEL, D_MODEL);

    // 2) fp16 tensor-core causal flash attention -> yf
    attn_tc<<<dim3(SEQ / 128, NUM_HEADS, BATCH), 256, AT_SMEM>>>(qkvh, qkvl, yf);

    // 3) Output projection -> fp32 out
    gemm_f16<false><<<dim3(D_MODEL / 128, ROWS / 128), 256, GEMM_SMEM>>>(
        yf, w2f, out, nullptr, nullptr, ROWS, D_MODEL, D_MODEL);
}

// round 10
// speedup vs baseline: 1.8426x; 1.0261x over previous
#include <cuda_runtime.h>
#include <cuda_fp16.h>
#include <cstdint>

#define D_MODEL   1024
#define NUM_HEADS 16
#define D_HEAD    64
#define BATCH     2
#define SEQ       2048
#define ROWS      (BATCH * SEQ)   // 4096

// ---------------------------------------------------------------------------
// Scratch (alloc-free rule: __device__ globals)
// ---------------------------------------------------------------------------
__device__ __half g_qkvh[(size_t)ROWS * 3 * D_MODEL];    // qkv fp16 hi
__device__ __half g_qkvl[(size_t)ROWS * 3 * D_MODEL];    // qkv fp16 residual lo
__device__ __half g_xf[(size_t)ROWS * D_MODEL];          // x as fp16
__device__ __half g_w1f[(size_t)3 * D_MODEL * D_MODEL];  // Wqkv fp16 (Q rows /8)
__device__ __half g_w2f[(size_t)D_MODEL * D_MODEL];      // Wout fp16
__device__ __half g_yf[(size_t)ROWS * D_MODEL];          // attention out, fp16

// ---------------------------------------------------------------------------
__device__ __forceinline__ uint32_t smem_u32(const void* p) {
    uint32_t a;
    asm("{ .reg .u64 t; cvta.to.shared.u64 t, %1; cvt.u32.u64 %0, t; }"
        : "=r"(a) : "l"(p));
    return a;
}

__device__ __forceinline__ void cp_async16(uint32_t dst, const void* src) {
    asm volatile("cp.async.cg.shared.global [%0], [%1], 16;" :: "r"(dst), "l"(src));
}

// fp16 MMA
__device__ __forceinline__ void mma16816h(float* c, const uint32_t* a, const uint32_t* b) {
    asm volatile(
        "mma.sync.aligned.m16n8k16.row.col.f32.f16.f16.f32 "
        "{%0,%1,%2,%3}, {%4,%5,%6,%7}, {%8,%9}, {%0,%1,%2,%3};"
        : "+f"(c[0]), "+f"(c[1]), "+f"(c[2]), "+f"(c[3])
        : "r"(a[0]), "r"(a[1]), "r"(a[2]), "r"(a[3]), "r"(b[0]), "r"(b[1]));
}

__device__ __forceinline__ void ldsm_x4(uint32_t* r, uint32_t addr) {
    asm volatile("ldmatrix.sync.aligned.m8n8.x4.shared.b16 {%0,%1,%2,%3}, [%4];"
        : "=r"(r[0]), "=r"(r[1]), "=r"(r[2]), "=r"(r[3]) : "r"(addr));
}

__device__ __forceinline__ void ldsm_x4_t(uint32_t* r, uint32_t addr) {
    asm volatile("ldmatrix.sync.aligned.m8n8.x4.trans.shared.b16 {%0,%1,%2,%3}, [%4];"
        : "=r"(r[0]), "=r"(r[1]), "=r"(r[2]), "=r"(r[3]) : "r"(addr));
}

__device__ __forceinline__ uint32_t pack_f16x2(float x, float y) {
    uint32_t r;
    asm("cvt.rn.f16x2.f32 %0, %1, %2;" : "=r"(r) : "f"(y), "f"(x));
    return r;
}

// pack two fp32 -> fp16x2 hi word + fp16x2 residual lo word
__device__ __forceinline__ void pack_f16_hilo(float x, float y, uint32_t& hp, uint32_t& lp) {
    asm("cvt.rn.f16x2.f32 %0, %1, %2;" : "=r"(hp) : "f"(y), "f"(x));
    __half2 h2 = *reinterpret_cast<__half2*>(&hp);
    float2 f = __half22float2(h2);
    lp = pack_f16x2(x - f.x, y - f.y);
}

// ---------------------------------------------------------------------------
// fp32 -> fp16 convert; first scale4_until float4s scaled by `sc` (else 1.0)
// ---------------------------------------------------------------------------
__global__ __launch_bounds__(256) void conv_f16(const float* __restrict__ src,
                                                __half* __restrict__ dst,
                                                int n4, int scale4_until, float sc) {
    int i = blockIdx.x * blockDim.x + threadIdx.x;
    if (i >= n4) return;
    float s = (i < scale4_until) ? sc : 1.0f;
    float4 v = ((const float4*)src)[i];
    uint32_t p0 = pack_f16x2(v.x * s, v.y * s);
    uint32_t p1 = pack_f16x2(v.z * s, v.w * s);
    ((uint2*)dst)[i] = make_uint2(p0, p1);
}

// ---------------------------------------------------------------------------
// fp16 GEMM NT: C[m,n] = sum_k A[m,k]*B[n,k]
// Block 128x128, BK=64, 8 warps (warp 64x32), 3-stage cp.async, 2 CTAs/SM.
// Frag-ldsm hoisted ahead of each 16-MMA block for latency overlap.
// ---------------------------------------------------------------------------
#define SROW       72                    // fp16 elems per smem row (144 B)
#define TILE_B     (128 * SROW * 2)      // 18432 B per tile
#define STAGE_B    (2 * TILE_B)          // A, B = 36864 B
#define NSTAGE     3
#define GEMM_SMEM  (NSTAGE * STAGE_B)    // 110592 B

__device__ __forceinline__ void load_stage(uint32_t s_base,
                                           const __half* Af, const __half* Bf,
                                           int m0, int n0, int k0, int K, int tid) {
#pragma unroll
    for (int p = 0; p < 4; p++) {
        int v = tid + p * 256;           // 0..1023
        int row = v >> 3;
        int c = v & 7;
        uint32_t soff = (uint32_t)(row * (SROW * 2) + c * 16);
        cp_async16(s_base + soff,
                   Af + (size_t)(m0 + row) * K + k0 + c * 8);
        cp_async16(s_base + TILE_B + soff,
                   Bf + (size_t)(n0 + row) * K + k0 + c * 8);
    }
}

template <bool F16OUT>
__global__ __launch_bounds__(256, 2) void gemm_f16(const __half* __restrict__ Af,
                                                   const __half* __restrict__ Bf,
                                                   float* __restrict__ C,
                                                   __half* __restrict__ Ch,
                                                   __half* __restrict__ Cl,
                                                   int M, int N, int K) {
    extern __shared__ __half smem[];
    const uint32_t sbase = smem_u32(smem);

    const int tid = threadIdx.x;
    const int wid = tid >> 5;
    const int lane = tid & 31;
    const int g = lane >> 2;
    const int t = lane & 3;
    const int m0 = blockIdx.y * 128;
    const int n0 = blockIdx.x * 128;
    const int wm = (wid >> 2) * 64;
    const int wn = (wid & 3) * 32;

    const int lrow  = (lane & 7) + 8 * ((lane >> 3) & 1);   // A frag
    const int lcol8 = 8 * (lane >> 4);
    const int lrowK = (lane & 7) + 8 * (lane >> 4);          // B frag
    const int lcol8K = 8 * ((lane >> 3) & 1);

    float acc[4][4][4];
#pragma unroll
    for (int mi = 0; mi < 4; mi++)
#pragma unroll
        for (int ni = 0; ni < 4; ni++)
#pragma unroll
            for (int r = 0; r < 4; r++) acc[mi][ni][r] = 0.f;

    const int NIT = K / 64;   // 16

    // Prologue: stages 0,1
#pragma unroll
    for (int s = 0; s < NSTAGE - 1; s++) {
        load_stage(sbase + s * STAGE_B, Af, Bf, m0, n0, s * 64, K, tid);
        asm volatile("cp.async.commit_group;" ::: "memory");
    }

    for (int it = 0; it < NIT; it++) {
        if (it + NSTAGE - 1 < NIT) {
            load_stage(sbase + ((it + NSTAGE - 1) % NSTAGE) * STAGE_B, Af, Bf,
                       m0, n0, (it + NSTAGE - 1) * 64, K, tid);
        }
        asm volatile("cp.async.commit_group;" ::: "memory");
        asm volatile("cp.async.wait_group %0;" :: "n"(NSTAGE - 1) : "memory");
        __syncthreads();

        const uint32_t sA = sbase + (it % NSTAGE) * STAGE_B;
        const uint32_t sB = sA + TILE_B;

#pragma unroll
        for (int ks = 0; ks < 4; ks++) {
            const int kb = ks * 16;
            // hoist ALL fragment loads ahead of the MMA block
            uint32_t a[4][4], b[2][4];
#pragma unroll
            for (int np = 0; np < 2; np++) {
                uint32_t boff = (uint32_t)((wn + np * 16 + lrowK) * (SROW * 2)
                                           + (kb + lcol8K) * 2);
                ldsm_x4(b[np], sB + boff);
            }
#pragma unroll
            for (int mi = 0; mi < 4; mi++) {
                uint32_t aoff = (uint32_t)((wm + mi * 16 + lrow) * (SROW * 2)
                                           + (kb + lcol8) * 2);
                ldsm_x4(a[mi], sA + aoff);
            }
#pragma unroll
            for (int mi = 0; mi < 4; mi++)
#pragma unroll
                for (int np = 0; np < 2; np++) {
                    mma16816h(acc[mi][2 * np],     a[mi], b[np]);
                    mma16816h(acc[mi][2 * np + 1], a[mi], b[np] + 2);
                }
        }
        __syncthreads();
    }

#pragma unroll
    for (int mi = 0; mi < 4; mi++) {
        int row0 = m0 + wm + mi * 16 + g;
#pragma unroll
        for (int ni = 0; ni < 4; ni++) {
            int col = n0 + wn + ni * 8 + 2 * t;
            if (F16OUT) {
                uint32_t hp, lp;
                pack_f16_hilo(acc[mi][ni][0], acc[mi][ni][1], hp, lp);
                *(uint32_t*)&Ch[(size_t)row0 * N + col] = hp;
                *(uint32_t*)&Cl[(size_t)row0 * N + col] = lp;
                pack_f16_hilo(acc[mi][ni][2], acc[mi][ni][3], hp, lp);
                *(uint32_t*)&Ch[(size_t)(row0 + 8) * N + col] = hp;
                *(uint32_t*)&Cl[(size_t)(row0 + 8) * N + col] = lp;
            } else {
                *(float2*)&C[(size_t)row0 * N + col] =
                    make_float2(acc[mi][ni][0], acc[mi][ni][1]);
                *(float2*)&C[(size_t)(row0 + 8) * N + col] =
                    make_float2(acc[mi][ni][2], acc[mi][ni][3]);
            }
        }
    }
}

// ---------------------------------------------------------------------------
// fp16 tensor-core causal flash attention. BQ=128, BK=64, Dh=64, 256 threads.
// qkv pre-split fp16 hi/lo. S = Qh*(Kh+Kl); O += f16(P)*(Vh+Vl).
// K/V double-buffered cp.async. LPT scheduling: heaviest q-tiles first.
// ---------------------------------------------------------------------------
#define AT_STAGE 36864
#define AT_SMEM  (18432 + 2 * AT_STAGE)   // 92160

__device__ __forceinline__ void load_kv(uint32_t stage_base,
                                        const __half* kh, const __half* kl,
                                        const __half* vh, const __half* vl,
                                        int k0, int tid) {
#pragma unroll
    for (int p = 0; p < 2; p++) {
        int v = tid + p * 256;        // 0..511
        int row = v >> 3, c = v & 7;
        size_t go = (size_t)(k0 + row) * (3 * D_MODEL) + c * 8;
        uint32_t soff = (uint32_t)(row * 144 + c * 16);
        cp_async16(stage_base + soff,             kh + go);
        cp_async16(stage_base + 9216 + soff,      kl + go);
        cp_async16(stage_base + 18432 + soff,     vh + go);
        cp_async16(stage_base + 27648 + soff,     vl + go);
    }
}

__global__ __launch_bounds__(256, 2) void attn_tc(const __half* __restrict__ qkvh,
                                                  const __half* __restrict__ qkvl,
                                                  __half* __restrict__ yf) {
    extern __shared__ __half asmem[];
    const uint32_t sb = smem_u32(asmem);
    const uint32_t QH = sb;
    const uint32_t ST0 = sb + 18432;

    const int tid = threadIdx.x;
    const int wid = tid >> 5;
    const int lane = tid & 31;
    const int g = lane >> 2, t = lane & 3;
    // LPT: heaviest q-tiles (largest qt) scheduled first
    const int qt = (gridDim.x - 1) - blockIdx.x;
    const int h = blockIdx.y, b = blockIdx.z;
    const int q0 = qt * 128;

    const size_t rowstride = 3 * D_MODEL;
    const __half* qh = qkvh + (size_t)b * SEQ * rowstride + h * D_HEAD;
    const __half* kh = qh + D_MODEL;
    const __half* vh = qh + 2 * D_MODEL;
    const __half* kl = qkvl + (size_t)b * SEQ * rowstride + h * D_HEAD + D_MODEL;
    const __half* vl = kl + D_MODEL;

    const int lrow  = (lane & 7) + 8 * ((lane >> 3) & 1);
    const int lcol8 = 8 * (lane >> 4);
    const int lrowK = (lane & 7) + 8 * (lane >> 4);
    const int lcol8K = 8 * ((lane >> 3) & 1);

    // ---- async-load Q hi tile ----
#pragma unroll
    for (int p = 0; p < 4; p++) {
        int v = tid + p * 256;
        int row = v >> 3, c = v & 7;
        cp_async16(QH + row * 144 + c * 16,
                   qh + (size_t)(q0 + row) * rowstride + c * 8);
    }
    asm volatile("cp.async.commit_group;" ::: "memory");

    load_kv(ST0, kh, kl, vh, vl, 0, tid);
    asm volatile("cp.async.commit_group;" ::: "memory");

    float m_[2] = {-1e30f, -1e30f};
    float l_[2] = {0.f, 0.f};
    float o[8][4];
#pragma unroll
    for (int nt = 0; nt < 8; nt++)
#pragma unroll
        for (int c = 0; c < 4; c++) o[nt][c] = 0.f;

    const int ntiles = 2 * qt + 2;
    for (int kt = 0; kt < ntiles; kt++) {
        const uint32_t CUR = ST0 + (kt & 1) * AT_STAGE;
        if (kt + 1 < ntiles) {
            load_kv(ST0 + ((kt + 1) & 1) * AT_STAGE, kh, kl, vh, vl,
                    (kt + 1) * 64, tid);
            asm volatile("cp.async.commit_group;" ::: "memory");
            asm volatile("cp.async.wait_group 1;" ::: "memory");
        } else {
            asm volatile("cp.async.wait_group 0;" ::: "memory");
        }
        __syncthreads();

        const uint32_t KHs = CUR, KLs = CUR + 9216, VHs = CUR + 18432, VLs = CUR + 27648;

        float s[8][4];
#pragma unroll
        for (int nt = 0; nt < 8; nt++)
#pragma unroll
            for (int c = 0; c < 4; c++) s[nt][c] = 0.f;

#pragma unroll
        for (int ks = 0; ks < 4; ks++) {
            uint32_t a[4];
            uint32_t qoff = (uint32_t)((wid * 16 + lrow) * 144 + (ks * 16 + lcol8) * 2);
            ldsm_x4(a, QH + qoff);
#pragma unroll
            for (int ntp = 0; ntp < 4; ntp++) {
                uint32_t bh[4], bl[4];
                uint32_t koff = (uint32_t)((ntp * 16 + lrowK) * 144 + (ks * 16 + lcol8K) * 2);
                ldsm_x4(bh, KHs + koff);
                ldsm_x4(bl, KLs + koff);
                mma16816h(s[2 * ntp],     a, bh);
                mma16816h(s[2 * ntp],     a, bl);
                mma16816h(s[2 * ntp + 1], a, bh + 2);
                mma16816h(s[2 * ntp + 1], a, bl + 2);
            }
        }

        if (kt >= 2 * qt) {
#pragma unroll
            for (int nt = 0; nt < 8; nt++)
#pragma unroll
                for (int c = 0; c < 4; c++) {
                    int row = q0 + wid * 16 + g + (c >> 1) * 8;
                    int col = kt * 64 + nt * 8 + 2 * t + (c & 1);
                    if (col > row) s[nt][c] = -1e30f;
                }
        }

#pragma unroll
        for (int r = 0; r < 2; r++) {
            float mx = -1e30f;
#pragma unroll
            for (int nt = 0; nt < 8; nt++)
                mx = fmaxf(mx, fmaxf(s[nt][2 * r], s[nt][2 * r + 1]));
            mx = fmaxf(mx, __shfl_xor_sync(0xffffffffu, mx, 1));
            mx = fmaxf(mx, __shfl_xor_sync(0xffffffffu, mx, 2));
            float mnew = fmaxf(m_[r], mx);
            float corr = __expf(m_[r] - mnew);
            m_[r] = mnew;
            float ls = 0.f;
#pragma unroll
            for (int nt = 0; nt < 8; nt++) {
                float p0 = __expf(s[nt][2 * r] - mnew);
                float p1 = __expf(s[nt][2 * r + 1] - mnew);
                s[nt][2 * r] = p0;
                s[nt][2 * r + 1] = p1;
                ls += p0 + p1;
            }
            ls += __shfl_xor_sync(0xffffffffu, ls, 1);
            ls += __shfl_xor_sync(0xffffffffu, ls, 2);
            l_[r] = l_[r] * corr + ls;
#pragma unroll
            for (int nt = 0; nt < 8; nt++) {
                o[nt][2 * r] *= corr;
                o[nt][2 * r + 1] *= corr;
            }
        }

#pragma unroll
        for (int kc = 0; kc < 4; kc++) {
            uint32_t pa[4];
            pa[0] = pack_f16x2(s[2 * kc][0],     s[2 * kc][1]);
            pa[1] = pack_f16x2(s[2 * kc][2],     s[2 * kc][3]);
            pa[2] = pack_f16x2(s[2 * kc + 1][0], s[2 * kc + 1][1]);
            pa[3] = pack_f16x2(s[2 * kc + 1][2], s[2 * kc + 1][3]);
#pragma unroll
            for (int ntp = 0; ntp < 4; ntp++) {
                uint32_t bh[4], bl[4];
                uint32_t voff = (uint32_t)((kc * 16 + lrow) * 144 + (ntp * 16 + lcol8) * 2);
                ldsm_x4_t(bh, VHs + voff);
                ldsm_x4_t(bl, VLs + voff);
                mma16816h(o[2 * ntp],     pa, bh);
                mma16816h(o[2 * ntp],     pa, bl);
                mma16816h(o[2 * ntp + 1], pa, bh + 2);
                mma16816h(o[2 * ntp + 1], pa, bl + 2);
            }
        }
        __syncthreads();
    }

    {
        float inv0 = 1.f / l_[0];
        float inv1 = 1.f / l_[1];
        int row0 = q0 + wid * 16 + g;
        size_t t0 = (size_t)b * SEQ + row0;
#pragma unroll
        for (int nt = 0; nt < 8; nt++) {
            int col = h * D_HEAD + nt * 8 + 2 * t;
            *(uint32_t*)&yf[t0 * D_MODEL + col] =
                pack_f16x2(o[nt][0] * inv0, o[nt][1] * inv0);
            *(uint32_t*)&yf[(t0 + 8) * D_MODEL + col] =
                pack_f16x2(o[nt][2] * inv1, o[nt][3] * inv1);
        }
    }
}

// ---------------------------------------------------------------------------
extern "C" void kernel_launch(void* const* d_in, const int* in_sizes, int n_in,
                              void* d_out, int out_size) {
    const float* x    = (const float*)d_in[0];
    const float* Wqkv = (const float*)d_in[1];
    const float* Wout = (const float*)d_in[2];
    float* out = (float*)d_out;

    __half *qkvh, *qkvl, *xf, *w1f, *w2f, *yf;
    cudaGetSymbolAddress((void**)&qkvh, g_qkvh);
    cudaGetSymbolAddress((void**)&qkvl, g_qkvl);
    cudaGetSymbolAddress((void**)&xf, g_xf);
    cudaGetSymbolAddress((void**)&w1f, g_w1f);
    cudaGetSymbolAddress((void**)&w2f, g_w2f);
    cudaGetSymbolAddress((void**)&yf, g_yf);

    cudaFuncSetAttribute(gemm_f16<true>, cudaFuncAttributeMaxDynamicSharedMemorySize, GEMM_SMEM);
    cudaFuncSetAttribute(gemm_f16<false>, cudaFuncAttributeMaxDynamicSharedMemorySize, GEMM_SMEM);
    cudaFuncSetAttribute(attn_tc, cudaFuncAttributeMaxDynamicSharedMemorySize, AT_SMEM);

    // Converts (Wqkv Q-rows pre-scaled by 1/8 = attention scale, exact)
    {
        int n4 = ROWS * D_MODEL / 4;
        conv_f16<<<(n4 + 255) / 256, 256>>>(x, xf, n4, 0, 1.0f);
        int w1n4 = 3 * D_MODEL * D_MODEL / 4;
        conv_f16<<<(w1n4 + 255) / 256, 256>>>(Wqkv, w1f, w1n4,
                                              D_MODEL * D_MODEL / 4, 0.125f);
        int w2n4 = D_MODEL * D_MODEL / 4;
        conv_f16<<<(w2n4 + 255) / 256, 256>>>(Wout, w2f, w2n4, 0, 1.0f);
    }

    // 1) QKV projection -> fp16 hi/lo qkv
    gemm_f16<true><<<dim3(3 * D_MODEL / 128, ROWS / 128), 256, GEMM_SMEM>>>(
        xf, w1f, nullptr, qkvh, qkvl, ROWS, 3 * D_MODEL, D_MODEL);

    // 2) fp16 tensor-core causal flash attention (LPT order) -> yf
    attn_tc<<<dim3(SEQ / 128, NUM_HEADS, BATCH), 256, AT_SMEM>>>(qkvh, qkvl, yf);

    // 3) Output projection -> fp32 out
    gemm_f16<false><<<dim3(D_MODEL / 128, ROWS / 128), 256, GEMM_SMEM>>>(
        yf, w2f, out, nullptr, nullptr, ROWS, D_MODEL, D_MODEL);
}

// round 11
// speedup vs baseline: 2.4177x; 1.3121x over previous
#include <cuda_runtime.h>
#include <cuda_fp16.h>
#include <cstdint>

#define D_MODEL   1024
#define NUM_HEADS 16
#define D_HEAD    64
#define BATCH     2
#define SEQ       2048
#define ROWS      (BATCH * SEQ)   // 4096

// ---------------------------------------------------------------------------
// Scratch (alloc-free rule: __device__ globals)
// ---------------------------------------------------------------------------
__device__ __half g_qkvf[(size_t)ROWS * 3 * D_MODEL];    // qkv fp16
__device__ __half g_xf[(size_t)ROWS * D_MODEL];          // x as fp16
__device__ __half g_w1f[(size_t)3 * D_MODEL * D_MODEL];  // Wqkv fp16 (Q rows /8)
__device__ __half g_w2f[(size_t)D_MODEL * D_MODEL];      // Wout fp16
__device__ __half g_yf[(size_t)ROWS * D_MODEL];          // attention out, fp16

// ---------------------------------------------------------------------------
__device__ __forceinline__ uint32_t smem_u32(const void* p) {
    uint32_t a;
    asm("{ .reg .u64 t; cvta.to.shared.u64 t, %1; cvt.u32.u64 %0, t; }"
        : "=r"(a) : "l"(p));
    return a;
}

__device__ __forceinline__ void cp_async16(uint32_t dst, const void* src) {
    asm volatile("cp.async.cg.shared.global [%0], [%1], 16;" :: "r"(dst), "l"(src));
}

// fp16 MMA
__device__ __forceinline__ void mma16816h(float* c, const uint32_t* a, const uint32_t* b) {
    asm volatile(
        "mma.sync.aligned.m16n8k16.row.col.f32.f16.f16.f32 "
        "{%0,%1,%2,%3}, {%4,%5,%6,%7}, {%8,%9}, {%0,%1,%2,%3};"
        : "+f"(c[0]), "+f"(c[1]), "+f"(c[2]), "+f"(c[3])
        : "r"(a[0]), "r"(a[1]), "r"(a[2]), "r"(a[3]), "r"(b[0]), "r"(b[1]));
}

__device__ __forceinline__ void ldsm_x4(uint32_t* r, uint32_t addr) {
    asm volatile("ldmatrix.sync.aligned.m8n8.x4.shared.b16 {%0,%1,%2,%3}, [%4];"
        : "=r"(r[0]), "=r"(r[1]), "=r"(r[2]), "=r"(r[3]) : "r"(addr));
}

__device__ __forceinline__ void ldsm_x4_t(uint32_t* r, uint32_t addr) {
    asm volatile("ldmatrix.sync.aligned.m8n8.x4.trans.shared.b16 {%0,%1,%2,%3}, [%4];"
        : "=r"(r[0]), "=r"(r[1]), "=r"(r[2]), "=r"(r[3]) : "r"(addr));
}

__device__ __forceinline__ uint32_t pack_f16x2(float x, float y) {
    uint32_t r;
    asm("cvt.rn.f16x2.f32 %0, %1, %2;" : "=r"(r) : "f"(y), "f"(x));
    return r;
}

// ---------------------------------------------------------------------------
// fp32 -> fp16 convert; first scale4_until float4s scaled by `sc` (else 1.0)
// ---------------------------------------------------------------------------
__global__ __launch_bounds__(256) void conv_f16(const float* __restrict__ src,
                                                __half* __restrict__ dst,
                                                int n4, int scale4_until, float sc) {
    int i = blockIdx.x * blockDim.x + threadIdx.x;
    if (i >= n4) return;
    float s = (i < scale4_until) ? sc : 1.0f;
    float4 v = ((const float4*)src)[i];
    uint32_t p0 = pack_f16x2(v.x * s, v.y * s);
    uint32_t p1 = pack_f16x2(v.z * s, v.w * s);
    ((uint2*)dst)[i] = make_uint2(p0, p1);
}

// ---------------------------------------------------------------------------
// fp16 GEMM NT: C[m,n] = sum_k A[m,k]*B[n,k]
// Block 128x128, BK=64, 8 warps (warp 64x32), 3-stage cp.async, 2 CTAs/SM.
// F16OUT: write single fp16 (feeds attention / GEMM2) instead of fp32.
// ---------------------------------------------------------------------------
#define SROW       72                    // fp16 elems per smem row (144 B)
#define TILE_B     (128 * SROW * 2)      // 18432 B per tile
#define STAGE_B    (2 * TILE_B)          // A, B = 36864 B
#define NSTAGE     3
#define GEMM_SMEM  (NSTAGE * STAGE_B)    // 110592 B

__device__ __forceinline__ void load_stage(uint32_t s_base,
                                           const __half* Af, const __half* Bf,
                                           int m0, int n0, int k0, int K, int tid) {
#pragma unroll
    for (int p = 0; p < 4; p++) {
        int v = tid + p * 256;           // 0..1023
        int row = v >> 3;
        int c = v & 7;
        uint32_t soff = (uint32_t)(row * (SROW * 2) + c * 16);
        cp_async16(s_base + soff,
                   Af + (size_t)(m0 + row) * K + k0 + c * 8);
        cp_async16(s_base + TILE_B + soff,
                   Bf + (size_t)(n0 + row) * K + k0 + c * 8);
    }
}

template <bool F16OUT>
__global__ __launch_bounds__(256, 2) void gemm_f16(const __half* __restrict__ Af,
                                                   const __half* __restrict__ Bf,
                                                   float* __restrict__ C,
                                                   __half* __restrict__ Cf,
                                                   int M, int N, int K) {
    extern __shared__ __half smem[];
    const uint32_t sbase = smem_u32(smem);

    const int tid = threadIdx.x;
    const int wid = tid >> 5;
    const int lane = tid & 31;
    const int g = lane >> 2;
    const int t = lane & 3;
    const int m0 = blockIdx.y * 128;
    const int n0 = blockIdx.x * 128;
    const int wm = (wid >> 2) * 64;
    const int wn = (wid & 3) * 32;

    const int lrow  = (lane & 7) + 8 * ((lane >> 3) & 1);   // A frag
    const int lcol8 = 8 * (lane >> 4);
    const int lrowK = (lane & 7) + 8 * (lane >> 4);          // B frag
    const int lcol8K = 8 * ((lane >> 3) & 1);

    float acc[4][4][4];
#pragma unroll
    for (int mi = 0; mi < 4; mi++)
#pragma unroll
        for (int ni = 0; ni < 4; ni++)
#pragma unroll
            for (int r = 0; r < 4; r++) acc[mi][ni][r] = 0.f;

    const int NIT = K / 64;   // 16

    // Prologue: stages 0,1
#pragma unroll
    for (int s = 0; s < NSTAGE - 1; s++) {
        load_stage(sbase + s * STAGE_B, Af, Bf, m0, n0, s * 64, K, tid);
        asm volatile("cp.async.commit_group;" ::: "memory");
    }

    for (int it = 0; it < NIT; it++) {
        if (it + NSTAGE - 1 < NIT) {
            load_stage(sbase + ((it + NSTAGE - 1) % NSTAGE) * STAGE_B, Af, Bf,
                       m0, n0, (it + NSTAGE - 1) * 64, K, tid);
        }
        asm volatile("cp.async.commit_group;" ::: "memory");
        asm volatile("cp.async.wait_group %0;" :: "n"(NSTAGE - 1) : "memory");
        __syncthreads();

        const uint32_t sA = sbase + (it % NSTAGE) * STAGE_B;
        const uint32_t sB = sA + TILE_B;

#pragma unroll
        for (int ks = 0; ks < 4; ks++) {
            const int kb = ks * 16;
            // hoist ALL fragment loads ahead of the MMA block
            uint32_t a[4][4], b[2][4];
#pragma unroll
            for (int np = 0; np < 2; np++) {
                uint32_t boff = (uint32_t)((wn + np * 16 + lrowK) * (SROW * 2)
                                           + (kb + lcol8K) * 2);
                ldsm_x4(b[np], sB + boff);
            }
#pragma unroll
            for (int mi = 0; mi < 4; mi++) {
                uint32_t aoff = (uint32_t)((wm + mi * 16 + lrow) * (SROW * 2)
                                           + (kb + lcol8) * 2);
                ldsm_x4(a[mi], sA + aoff);
            }
#pragma unroll
            for (int mi = 0; mi < 4; mi++)
#pragma unroll
                for (int np = 0; np < 2; np++) {
                    mma16816h(acc[mi][2 * np],     a[mi], b[np]);
                    mma16816h(acc[mi][2 * np + 1], a[mi], b[np] + 2);
                }
        }
        __syncthreads();
    }

#pragma unroll
    for (int mi = 0; mi < 4; mi++) {
        int row0 = m0 + wm + mi * 16 + g;
#pragma unroll
        for (int ni = 0; ni < 4; ni++) {
            int col = n0 + wn + ni * 8 + 2 * t;
            if (F16OUT) {
                *(uint32_t*)&Cf[(size_t)row0 * N + col] =
                    pack_f16x2(acc[mi][ni][0], acc[mi][ni][1]);
                *(uint32_t*)&Cf[(size_t)(row0 + 8) * N + col] =
                    pack_f16x2(acc[mi][ni][2], acc[mi][ni][3]);
            } else {
                *(float2*)&C[(size_t)row0 * N + col] =
                    make_float2(acc[mi][ni][0], acc[mi][ni][1]);
                *(float2*)&C[(size_t)(row0 + 8) * N + col] =
                    make_float2(acc[mi][ni][2], acc[mi][ni][3]);
            }
        }
    }
}

// ---------------------------------------------------------------------------
// fp16 tensor-core causal flash attention. BQ=128, BK=64, Dh=64, 256 threads.
// Q, K, V single fp16. S = Q*K^T; O += f16(P)*V.
// K/V triple-buffered cp.async. LPT scheduling: heaviest q-tiles first.
// smem: Q 18432 | 3 stages x (K 9216, V 9216) = 73728 B
// ---------------------------------------------------------------------------
#define AT_STAGE 18432
#define AT_SMEM  (18432 + 3 * AT_STAGE)   // 73728

__device__ __forceinline__ void load_kv(uint32_t stage_base,
                                        const __half* kf, const __half* vf,
                                        int k0, int tid) {
#pragma unroll
    for (int p = 0; p < 2; p++) {
        int v = tid + p * 256;        // 0..511
        int row = v >> 3, c = v & 7;
        size_t go = (size_t)(k0 + row) * (3 * D_MODEL) + c * 8;
        uint32_t soff = (uint32_t)(row * 144 + c * 16);
        cp_async16(stage_base + soff,        kf + go);
        cp_async16(stage_base + 9216 + soff, vf + go);
    }
}

__global__ __launch_bounds__(256, 2) void attn_tc(const __half* __restrict__ qkvf,
                                                  __half* __restrict__ yf) {
    extern __shared__ __half asmem[];
    const uint32_t sb = smem_u32(asmem);
    const uint32_t QS = sb;
    const uint32_t ST0 = sb + 18432;

    const int tid = threadIdx.x;
    const int wid = tid >> 5;
    const int lane = tid & 31;
    const int g = lane >> 2, t = lane & 3;
    // LPT: heaviest q-tiles (largest qt) scheduled first
    const int qt = (gridDim.x - 1) - blockIdx.x;
    const int h = blockIdx.y, b = blockIdx.z;
    const int q0 = qt * 128;

    const size_t rowstride = 3 * D_MODEL;
    const __half* qf = qkvf + (size_t)b * SEQ * rowstride + h * D_HEAD;
    const __half* kf = qf + D_MODEL;
    const __half* vf = qf + 2 * D_MODEL;

    const int lrow  = (lane & 7) + 8 * ((lane >> 3) & 1);
    const int lcol8 = 8 * (lane >> 4);
    const int lrowK = (lane & 7) + 8 * (lane >> 4);
    const int lcol8K = 8 * ((lane >> 3) & 1);

    // ---- async-load Q tile ----
#pragma unroll
    for (int p = 0; p < 4; p++) {
        int v = tid + p * 256;
        int row = v >> 3, c = v & 7;
        cp_async16(QS + row * 144 + c * 16,
                   qf + (size_t)(q0 + row) * rowstride + c * 8);
    }
    asm volatile("cp.async.commit_group;" ::: "memory");

    const int ntiles = 2 * qt + 2;
    // Prologue: KV stages 0,1 (ntiles >= 2 always)
    load_kv(ST0, kf, vf, 0, tid);
    asm volatile("cp.async.commit_group;" ::: "memory");
    load_kv(ST0 + AT_STAGE, kf, vf, 64, tid);
    asm volatile("cp.async.commit_group;" ::: "memory");

    float m_[2] = {-1e30f, -1e30f};
    float l_[2] = {0.f, 0.f};
    float o[8][4];
#pragma unroll
    for (int nt = 0; nt < 8; nt++)
#pragma unroll
        for (int c = 0; c < 4; c++) o[nt][c] = 0.f;

    for (int kt = 0; kt < ntiles; kt++) {
        const uint32_t CUR = ST0 + (kt % 3) * AT_STAGE;
        if (kt + 2 < ntiles) {
            load_kv(ST0 + ((kt + 2) % 3) * AT_STAGE, kf, vf, (kt + 2) * 64, tid);
        }
        asm volatile("cp.async.commit_group;" ::: "memory");
        asm volatile("cp.async.wait_group 2;" ::: "memory");
        __syncthreads();

        const uint32_t KS = CUR, VS = CUR + 9216;

        // ---- S = Q K^T ----
        float s[8][4];
#pragma unroll
        for (int nt = 0; nt < 8; nt++)
#pragma unroll
            for (int c = 0; c < 4; c++) s[nt][c] = 0.f;

#pragma unroll
        for (int ks = 0; ks < 4; ks++) {
            uint32_t a[4];
            uint32_t qoff = (uint32_t)((wid * 16 + lrow) * 144 + (ks * 16 + lcol8) * 2);
            ldsm_x4(a, QS + qoff);
#pragma unroll
            for (int ntp = 0; ntp < 4; ntp++) {
                uint32_t bk[4];
                uint32_t koff = (uint32_t)((ntp * 16 + lrowK) * 144 + (ks * 16 + lcol8K) * 2);
                ldsm_x4(bk, KS + koff);
                mma16816h(s[2 * ntp],     a, bk);
                mma16816h(s[2 * ntp + 1], a, bk + 2);
            }
        }

        // ---- causal mask ----
        if (kt >= 2 * qt) {
#pragma unroll
            for (int nt = 0; nt < 8; nt++)
#pragma unroll
                for (int c = 0; c < 4; c++) {
                    int row = q0 + wid * 16 + g + (c >> 1) * 8;
                    int col = kt * 64 + nt * 8 + 2 * t + (c & 1);
                    if (col > row) s[nt][c] = -1e30f;
                }
        }

        // ---- online softmax ----
#pragma unroll
        for (int r = 0; r < 2; r++) {
            float mx = -1e30f;
#pragma unroll
            for (int nt = 0; nt < 8; nt++)
                mx = fmaxf(mx, fmaxf(s[nt][2 * r], s[nt][2 * r + 1]));
            mx = fmaxf(mx, __shfl_xor_sync(0xffffffffu, mx, 1));
            mx = fmaxf(mx, __shfl_xor_sync(0xffffffffu, mx, 2));
            float mnew = fmaxf(m_[r], mx);
            float corr = __expf(m_[r] - mnew);
            m_[r] = mnew;
            float ls = 0.f;
#pragma unroll
            for (int nt = 0; nt < 8; nt++) {
                float p0 = __expf(s[nt][2 * r] - mnew);
                float p1 = __expf(s[nt][2 * r + 1] - mnew);
                s[nt][2 * r] = p0;
                s[nt][2 * r + 1] = p1;
                ls += p0 + p1;
            }
            ls += __shfl_xor_sync(0xffffffffu, ls, 1);
            ls += __shfl_xor_sync(0xffffffffu, ls, 2);
            l_[r] = l_[r] * corr + ls;
#pragma unroll
            for (int nt = 0; nt < 8; nt++) {
                o[nt][2 * r] *= corr;
                o[nt][2 * r + 1] *= corr;
            }
        }

        // ---- O += f16(P) V ----
#pragma unroll
        for (int kc = 0; kc < 4; kc++) {
            uint32_t pa[4];
            pa[0] = pack_f16x2(s[2 * kc][0],     s[2 * kc][1]);
            pa[1] = pack_f16x2(s[2 * kc][2],     s[2 * kc][3]);
            pa[2] = pack_f16x2(s[2 * kc + 1][0], s[2 * kc + 1][1]);
            pa[3] = pack_f16x2(s[2 * kc + 1][2], s[2 * kc + 1][3]);
#pragma unroll
            for (int ntp = 0; ntp < 4; ntp++) {
                uint32_t bv[4];
                uint32_t voff = (uint32_t)((kc * 16 + lrow) * 144 + (ntp * 16 + lcol8) * 2);
                ldsm_x4_t(bv, VS + voff);
                mma16816h(o[2 * ntp],     pa, bv);
                mma16816h(o[2 * ntp + 1], pa, bv + 2);
            }
        }
        __syncthreads();   // all reads of CUR stage done before it is reloaded
    }

    // ---- epilogue: normalize + write y as fp16 ----
    {
        float inv0 = 1.f / l_[0];
        float inv1 = 1.f / l_[1];
        int row0 = q0 + wid * 16 + g;
        size_t t0 = (size_t)b * SEQ + row0;
#pragma unroll
        for (int nt = 0; nt < 8; nt++) {
            int col = h * D_HEAD + nt * 8 + 2 * t;
            *(uint32_t*)&yf[t0 * D_MODEL + col] =
                pack_f16x2(o[nt][0] * inv0, o[nt][1] * inv0);
            *(uint32_t*)&yf[(t0 + 8) * D_MODEL + col] =
                pack_f16x2(o[nt][2] * inv1, o[nt][3] * inv1);
        }
    }
}

// ---------------------------------------------------------------------------
extern "C" void kernel_launch(void* const* d_in, const int* in_sizes, int n_in,
                              void* d_out, int out_size) {
    const float* x    = (const float*)d_in[0];
    const float* Wqkv = (const float*)d_in[1];
    const float* Wout = (const float*)d_in[2];
    float* out = (float*)d_out;

    __half *qkvf, *xf, *w1f, *w2f, *yf;
    cudaGetSymbolAddress((void**)&qkvf, g_qkvf);
    cudaGetSymbolAddress((void**)&xf, g_xf);
    cudaGetSymbolAddress((void**)&w1f, g_w1f);
    cudaGetSymbolAddress((void**)&w2f, g_w2f);
    cudaGetSymbolAddress((void**)&yf, g_yf);

    cudaFuncSetAttribute(gemm_f16<true>, cudaFuncAttributeMaxDynamicSharedMemorySize, GEMM_SMEM);
    cudaFuncSetAttribute(gemm_f16<false>, cudaFuncAttributeMaxDynamicSharedMemorySize, GEMM_SMEM);
    cudaFuncSetAttribute(attn_tc, cudaFuncAttributeMaxDynamicSharedMemorySize, AT_SMEM);

    // Converts (Wqkv Q-rows pre-scaled by 1/8 = attention scale, exact)
    {
        int n4 = ROWS * D_MODEL / 4;
        conv_f16<<<(n4 + 255) / 256, 256>>>(x, xf, n4, 0, 1.0f);
        int w1n4 = 3 * D_MODEL * D_MODEL / 4;
        conv_f16<<<(w1n4 + 255) / 256, 256>>>(Wqkv, w1f, w1n4,
                                              D_MODEL * D_MODEL / 4, 0.125f);
        int w2n4 = D_MODEL * D_MODEL / 4;
        conv_f16<<<(w2n4 + 255) / 256, 256>>>(Wout, w2f, w2n4, 0, 1.0f);
    }

    // 1) QKV projection -> fp16 qkv
    gemm_f16<true><<<dim3(3 * D_MODEL / 128, ROWS / 128), 256, GEMM_SMEM>>>(
        xf, w1f, nullptr, qkvf, ROWS, 3 * D_MODEL, D_MODEL);

    // 2) fp16 tensor-core causal flash attention (LPT order) -> yf
    attn_tc<<<dim3(SEQ / 128, NUM_HEADS, BATCH), 256, AT_SMEM>>>(qkvf, yf);

    // 3) Output projection -> fp32 out
    gemm_f16<false><<<dim3(D_MODEL / 128, ROWS / 128), 256, GEMM_SMEM>>>(
        yf, w2f, out, nullptr, ROWS, D_MODEL, D_MODEL);
}

// round 12
// speedup vs baseline: 2.4335x; 1.0065x over previous
#include <cuda_runtime.h>
#include <cuda_fp16.h>
#include <cstdint>

#define D_MODEL   1024
#define NUM_HEADS 16
#define D_HEAD    64
#define BATCH     2
#define SEQ       2048
#define ROWS      (BATCH * SEQ)   // 4096

// ---------------------------------------------------------------------------
// Scratch (alloc-free rule: __device__ globals)
// ---------------------------------------------------------------------------
__device__ __half g_qkvf[(size_t)ROWS * 3 * D_MODEL];    // qkv fp16
__device__ __half g_xf[(size_t)ROWS * D_MODEL];          // x as fp16
__device__ __half g_w1f[(size_t)3 * D_MODEL * D_MODEL];  // Wqkv fp16 (Q rows scaled)
__device__ __half g_w2f[(size_t)D_MODEL * D_MODEL];      // Wout fp16
__device__ __half g_yf[(size_t)ROWS * D_MODEL];          // attention out, fp16

// ---------------------------------------------------------------------------
__device__ __forceinline__ uint32_t smem_u32(const void* p) {
    uint32_t a;
    asm("{ .reg .u64 t; cvta.to.shared.u64 t, %1; cvt.u32.u64 %0, t; }"
        : "=r"(a) : "l"(p));
    return a;
}

__device__ __forceinline__ void cp_async16(uint32_t dst, const void* src) {
    asm volatile("cp.async.cg.shared.global [%0], [%1], 16;" :: "r"(dst), "l"(src));
}

// fp16 MMA
__device__ __forceinline__ void mma16816h(float* c, const uint32_t* a, const uint32_t* b) {
    asm volatile(
        "mma.sync.aligned.m16n8k16.row.col.f32.f16.f16.f32 "
        "{%0,%1,%2,%3}, {%4,%5,%6,%7}, {%8,%9}, {%0,%1,%2,%3};"
        : "+f"(c[0]), "+f"(c[1]), "+f"(c[2]), "+f"(c[3])
        : "r"(a[0]), "r"(a[1]), "r"(a[2]), "r"(a[3]), "r"(b[0]), "r"(b[1]));
}

__device__ __forceinline__ void ldsm_x4(uint32_t* r, uint32_t addr) {
    asm volatile("ldmatrix.sync.aligned.m8n8.x4.shared.b16 {%0,%1,%2,%3}, [%4];"
        : "=r"(r[0]), "=r"(r[1]), "=r"(r[2]), "=r"(r[3]) : "r"(addr));
}

__device__ __forceinline__ void ldsm_x4_t(uint32_t* r, uint32_t addr) {
    asm volatile("ldmatrix.sync.aligned.m8n8.x4.trans.shared.b16 {%0,%1,%2,%3}, [%4];"
        : "=r"(r[0]), "=r"(r[1]), "=r"(r[2]), "=r"(r[3]) : "r"(addr));
}

__device__ __forceinline__ uint32_t pack_f16x2(float x, float y) {
    uint32_t r;
    asm("cvt.rn.f16x2.f32 %0, %1, %2;" : "=r"(r) : "f"(y), "f"(x));
    return r;
}

// ---------------------------------------------------------------------------
// fp32 -> fp16 convert; first scale4_until float4s scaled by `sc` (else 1.0)
// ---------------------------------------------------------------------------
__global__ __launch_bounds__(256) void conv_f16(const float* __restrict__ src,
                                                __half* __restrict__ dst,
                                                int n4, int scale4_until, float sc) {
    int i = blockIdx.x * blockDim.x + threadIdx.x;
    if (i >= n4) return;
    float s = (i < scale4_until) ? sc : 1.0f;
    float4 v = ((const float4*)src)[i];
    uint32_t p0 = pack_f16x2(v.x * s, v.y * s);
    uint32_t p1 = pack_f16x2(v.z * s, v.w * s);
    ((uint2*)dst)[i] = make_uint2(p0, p1);
}

// ---------------------------------------------------------------------------
// fp16 GEMM NT: C[m,n] = sum_k A[m,k]*B[n,k]
// Block 128x128, BK=64, 8 warps (warp 64x32), 3-stage cp.async, 2 CTAs/SM.
// Fragment loads software-pipelined (double-buffered) across ks steps.
// ---------------------------------------------------------------------------
#define SROW       72                    // fp16 elems per smem row (144 B)
#define TILE_B     (128 * SROW * 2)      // 18432 B per tile
#define STAGE_B    (2 * TILE_B)          // A, B = 36864 B
#define NSTAGE     3
#define GEMM_SMEM  (NSTAGE * STAGE_B)    // 110592 B

__device__ __forceinline__ void load_stage(uint32_t s_base,
                                           const __half* Af, const __half* Bf,
                                           int m0, int n0, int k0, int K, int tid) {
#pragma unroll
    for (int p = 0; p < 4; p++) {
        int v = tid + p * 256;           // 0..1023
        int row = v >> 3;
        int c = v & 7;
        uint32_t soff = (uint32_t)(row * (SROW * 2) + c * 16);
        cp_async16(s_base + soff,
                   Af + (size_t)(m0 + row) * K + k0 + c * 8);
        cp_async16(s_base + TILE_B + soff,
                   Bf + (size_t)(n0 + row) * K + k0 + c * 8);
    }
}

template <bool F16OUT>
__global__ __launch_bounds__(256, 2) void gemm_f16(const __half* __restrict__ Af,
                                                   const __half* __restrict__ Bf,
                                                   float* __restrict__ C,
                                                   __half* __restrict__ Cf,
                                                   int M, int N, int K) {
    extern __shared__ __half smem[];
    const uint32_t sbase = smem_u32(smem);

    const int tid = threadIdx.x;
    const int wid = tid >> 5;
    const int lane = tid & 31;
    const int g = lane >> 2;
    const int t = lane & 3;
    const int m0 = blockIdx.y * 128;
    const int n0 = blockIdx.x * 128;
    const int wm = (wid >> 2) * 64;
    const int wn = (wid & 3) * 32;

    const int lrow  = (lane & 7) + 8 * ((lane >> 3) & 1);   // A frag
    const int lcol8 = 8 * (lane >> 4);
    const int lrowK = (lane & 7) + 8 * (lane >> 4);          // B frag
    const int lcol8K = 8 * ((lane >> 3) & 1);

    float acc[4][4][4];
#pragma unroll
    for (int mi = 0; mi < 4; mi++)
#pragma unroll
        for (int ni = 0; ni < 4; ni++)
#pragma unroll
            for (int r = 0; r < 4; r++) acc[mi][ni][r] = 0.f;

    const int NIT = K / 64;   // 16

    // Prologue: stages 0,1
#pragma unroll
    for (int s = 0; s < NSTAGE - 1; s++) {
        load_stage(sbase + s * STAGE_B, Af, Bf, m0, n0, s * 64, K, tid);
        asm volatile("cp.async.commit_group;" ::: "memory");
    }

    // per-warp base addresses (k-invariant parts)
    const uint32_t aBase = (uint32_t)((wm + lrow) * (SROW * 2) + lcol8 * 2);
    const uint32_t bBase = (uint32_t)((wn + lrowK) * (SROW * 2) + lcol8K * 2);

    for (int it = 0; it < NIT; it++) {
        if (it + NSTAGE - 1 < NIT) {
            load_stage(sbase + ((it + NSTAGE - 1) % NSTAGE) * STAGE_B, Af, Bf,
                       m0, n0, (it + NSTAGE - 1) * 64, K, tid);
        }
        asm volatile("cp.async.commit_group;" ::: "memory");
        asm volatile("cp.async.wait_group %0;" :: "n"(NSTAGE - 1) : "memory");
        __syncthreads();

        const uint32_t sA = sbase + (it % NSTAGE) * STAGE_B;
        const uint32_t sB = sA + TILE_B;

        // software-pipelined fragment loads (double buffer)
        uint32_t af[2][4][4], bf[2][2][4];
#pragma unroll
        for (int np = 0; np < 2; np++)
            ldsm_x4(bf[0][np], sB + bBase + np * 16 * (SROW * 2));
#pragma unroll
        for (int mi = 0; mi < 4; mi++)
            ldsm_x4(af[0][mi], sA + aBase + mi * 16 * (SROW * 2));

#pragma unroll
        for (int ks = 0; ks < 4; ks++) {
            const int cur = ks & 1, nxt = cur ^ 1;
            if (ks < 3) {
                const uint32_t ko = (uint32_t)((ks + 1) * 16 * 2);
#pragma unroll
                for (int np = 0; np < 2; np++)
                    ldsm_x4(bf[nxt][np], sB + bBase + np * 16 * (SROW * 2) + ko);
#pragma unroll
                for (int mi = 0; mi < 4; mi++)
                    ldsm_x4(af[nxt][mi], sA + aBase + mi * 16 * (SROW * 2) + ko);
            }
#pragma unroll
            for (int mi = 0; mi < 4; mi++)
#pragma unroll
                for (int np = 0; np < 2; np++) {
                    mma16816h(acc[mi][2 * np],     af[cur][mi], bf[cur][np]);
                    mma16816h(acc[mi][2 * np + 1], af[cur][mi], bf[cur][np] + 2);
                }
        }
        __syncthreads();
    }

#pragma unroll
    for (int mi = 0; mi < 4; mi++) {
        int row0 = m0 + wm + mi * 16 + g;
#pragma unroll
        for (int ni = 0; ni < 4; ni++) {
            int col = n0 + wn + ni * 8 + 2 * t;
            if (F16OUT) {
                *(uint32_t*)&Cf[(size_t)row0 * N + col] =
                    pack_f16x2(acc[mi][ni][0], acc[mi][ni][1]);
                *(uint32_t*)&Cf[(size_t)(row0 + 8) * N + col] =
                    pack_f16x2(acc[mi][ni][2], acc[mi][ni][3]);
            } else {
                *(float2*)&C[(size_t)row0 * N + col] =
                    make_float2(acc[mi][ni][0], acc[mi][ni][1]);
                *(float2*)&C[(size_t)(row0 + 8) * N + col] =
                    make_float2(acc[mi][ni][2], acc[mi][ni][3]);
            }
        }
    }
}

// ---------------------------------------------------------------------------
// fp16 tensor-core causal flash attention. BQ=128, BK=64, Dh=64, 256 threads.
// Q, K, V single fp16. Q pre-scaled by 0.125*log2(e) -> softmax in exp2 domain.
// K/V triple-buffered cp.async. LPT scheduling: heaviest q-tiles first.
// smem: Q 18432 | 3 stages x (K 9216, V 9216) = 73728 B
// ---------------------------------------------------------------------------
#define AT_STAGE 18432
#define AT_SMEM  (18432 + 3 * AT_STAGE)   // 73728

__device__ __forceinline__ void load_kv(uint32_t stage_base,
                                        const __half* kf, const __half* vf,
                                        int k0, int tid) {
#pragma unroll
    for (int p = 0; p < 2; p++) {
        int v = tid + p * 256;        // 0..511
        int row = v >> 3, c = v & 7;
        size_t go = (size_t)(k0 + row) * (3 * D_MODEL) + c * 8;
        uint32_t soff = (uint32_t)(row * 144 + c * 16);
        cp_async16(stage_base + soff,        kf + go);
        cp_async16(stage_base + 9216 + soff, vf + go);
    }
}

__global__ __launch_bounds__(256, 2) void attn_tc(const __half* __restrict__ qkvf,
                                                  __half* __restrict__ yf) {
    extern __shared__ __half asmem[];
    const uint32_t sb = smem_u32(asmem);
    const uint32_t QS = sb;
    const uint32_t ST0 = sb + 18432;

    const int tid = threadIdx.x;
    const int wid = tid >> 5;
    const int lane = tid & 31;
    const int g = lane >> 2, t = lane & 3;
    // LPT: heaviest q-tiles (largest qt) scheduled first
    const int qt = (gridDim.x - 1) - blockIdx.x;
    const int h = blockIdx.y, b = blockIdx.z;
    const int q0 = qt * 128;

    const size_t rowstride = 3 * D_MODEL;
    const __half* qf = qkvf + (size_t)b * SEQ * rowstride + h * D_HEAD;
    const __half* kf = qf + D_MODEL;
    const __half* vf = qf + 2 * D_MODEL;

    const int lrow  = (lane & 7) + 8 * ((lane >> 3) & 1);
    const int lcol8 = 8 * (lane >> 4);
    const int lrowK = (lane & 7) + 8 * (lane >> 4);
    const int lcol8K = 8 * ((lane >> 3) & 1);

    // ---- async-load Q tile ----
#pragma unroll
    for (int p = 0; p < 4; p++) {
        int v = tid + p * 256;
        int row = v >> 3, c = v & 7;
        cp_async16(QS + row * 144 + c * 16,
                   qf + (size_t)(q0 + row) * rowstride + c * 8);
    }
    asm volatile("cp.async.commit_group;" ::: "memory");

    const int ntiles = 2 * qt + 2;
    load_kv(ST0, kf, vf, 0, tid);
    asm volatile("cp.async.commit_group;" ::: "memory");
    load_kv(ST0 + AT_STAGE, kf, vf, 64, tid);
    asm volatile("cp.async.commit_group;" ::: "memory");

    float m_[2] = {-1e30f, -1e30f};
    float l_[2] = {0.f, 0.f};
    float o[8][4];
#pragma unroll
    for (int nt = 0; nt < 8; nt++)
#pragma unroll
        for (int c = 0; c < 4; c++) o[nt][c] = 0.f;

    for (int kt = 0; kt < ntiles; kt++) {
        const uint32_t CUR = ST0 + (kt % 3) * AT_STAGE;
        if (kt + 2 < ntiles) {
            load_kv(ST0 + ((kt + 2) % 3) * AT_STAGE, kf, vf, (kt + 2) * 64, tid);
        }
        asm volatile("cp.async.commit_group;" ::: "memory");
        asm volatile("cp.async.wait_group 2;" ::: "memory");
        __syncthreads();

        const uint32_t KS = CUR, VS = CUR + 9216;

        // ---- S = Q K^T (log2-domain scores) ----
        float s[8][4];
#pragma unroll
        for (int nt = 0; nt < 8; nt++)
#pragma unroll
            for (int c = 0; c < 4; c++) s[nt][c] = 0.f;

#pragma unroll
        for (int ks = 0; ks < 4; ks++) {
            uint32_t a[4];
            uint32_t qoff = (uint32_t)((wid * 16 + lrow) * 144 + (ks * 16 + lcol8) * 2);
            ldsm_x4(a, QS + qoff);
#pragma unroll
            for (int ntp = 0; ntp < 4; ntp++) {
                uint32_t bk[4];
                uint32_t koff = (uint32_t)((ntp * 16 + lrowK) * 144 + (ks * 16 + lcol8K) * 2);
                ldsm_x4(bk, KS + koff);
                mma16816h(s[2 * ntp],     a, bk);
                mma16816h(s[2 * ntp + 1], a, bk + 2);
            }
        }

        // ---- causal mask ----
        if (kt >= 2 * qt) {
#pragma unroll
            for (int nt = 0; nt < 8; nt++)
#pragma unroll
                for (int c = 0; c < 4; c++) {
                    int row = q0 + wid * 16 + g + (c >> 1) * 8;
                    int col = kt * 64 + nt * 8 + 2 * t + (c & 1);
                    if (col > row) s[nt][c] = -1e30f;
                }
        }

        // ---- online softmax (exp2 domain) ----
#pragma unroll
        for (int r = 0; r < 2; r++) {
            float mx = -1e30f;
#pragma unroll
            for (int nt = 0; nt < 8; nt++)
                mx = fmaxf(mx, fmaxf(s[nt][2 * r], s[nt][2 * r + 1]));
            mx = fmaxf(mx, __shfl_xor_sync(0xffffffffu, mx, 1));
            mx = fmaxf(mx, __shfl_xor_sync(0xffffffffu, mx, 2));
            float mnew = fmaxf(m_[r], mx);
            float corr = exp2f(m_[r] - mnew);
            m_[r] = mnew;
            float ls = 0.f;
#pragma unroll
            for (int nt = 0; nt < 8; nt++) {
                float p0 = exp2f(s[nt][2 * r] - mnew);
                float p1 = exp2f(s[nt][2 * r + 1] - mnew);
                s[nt][2 * r] = p0;
                s[nt][2 * r + 1] = p1;
                ls += p0 + p1;
            }
            ls += __shfl_xor_sync(0xffffffffu, ls, 1);
            ls += __shfl_xor_sync(0xffffffffu, ls, 2);
            l_[r] = l_[r] * corr + ls;
#pragma unroll
            for (int nt = 0; nt < 8; nt++) {
                o[nt][2 * r] *= corr;
                o[nt][2 * r + 1] *= corr;
            }
        }

        // ---- O += f16(P) V ----
#pragma unroll
        for (int kc = 0; kc < 4; kc++) {
            uint32_t pa[4];
            pa[0] = pack_f16x2(s[2 * kc][0],     s[2 * kc][1]);
            pa[1] = pack_f16x2(s[2 * kc][2],     s[2 * kc][3]);
            pa[2] = pack_f16x2(s[2 * kc + 1][0], s[2 * kc + 1][1]);
            pa[3] = pack_f16x2(s[2 * kc + 1][2], s[2 * kc + 1][3]);
#pragma unroll
            for (int ntp = 0; ntp < 4; ntp++) {
                uint32_t bv[4];
                uint32_t voff = (uint32_t)((kc * 16 + lrow) * 144 + (ntp * 16 + lcol8) * 2);
                ldsm_x4_t(bv, VS + voff);
                mma16816h(o[2 * ntp],     pa, bv);
                mma16816h(o[2 * ntp + 1], pa, bv + 2);
            }
        }
        __syncthreads();   // all reads of CUR stage done before it is reloaded
    }

    // ---- epilogue: normalize + write y as fp16 ----
    {
        float inv0 = 1.f / l_[0];
        float inv1 = 1.f / l_[1];
        int row0 = q0 + wid * 16 + g;
        size_t t0 = (size_t)b * SEQ + row0;
#pragma unroll
        for (int nt = 0; nt < 8; nt++) {
            int col = h * D_HEAD + nt * 8 + 2 * t;
            *(uint32_t*)&yf[t0 * D_MODEL + col] =
                pack_f16x2(o[nt][0] * inv0, o[nt][1] * inv0);
            *(uint32_t*)&yf[(t0 + 8) * D_MODEL + col] =
                pack_f16x2(o[nt][2] * inv1, o[nt][3] * inv1);
        }
    }
}

// ---------------------------------------------------------------------------
extern "C" void kernel_launch(void* const* d_in, const int* in_sizes, int n_in,
                              void* d_out, int out_size) {
    const float* x    = (const float*)d_in[0];
    const float* Wqkv = (const float*)d_in[1];
    const float* Wout = (const float*)d_in[2];
    float* out = (float*)d_out;

    __half *qkvf, *xf, *w1f, *w2f, *yf;
    cudaGetSymbolAddress((void**)&qkvf, g_qkvf);
    cudaGetSymbolAddress((void**)&xf, g_xf);
    cudaGetSymbolAddress((void**)&w1f, g_w1f);
    cudaGetSymbolAddress((void**)&w2f, g_w2f);
    cudaGetSymbolAddress((void**)&yf, g_yf);

    cudaFuncSetAttribute(gemm_f16<true>, cudaFuncAttributeMaxDynamicSharedMemorySize, GEMM_SMEM);
    cudaFuncSetAttribute(gemm_f16<false>, cudaFuncAttributeMaxDynamicSharedMemorySize, GEMM_SMEM);
    cudaFuncSetAttribute(attn_tc, cudaFuncAttributeMaxDynamicSharedMemorySize, AT_SMEM);

    // Converts. Wqkv Q-rows pre-scaled by (1/8)*log2(e): attention scale folded
    // into Q AND softmax moved to exp2 domain.
    {
        const float QSCALE = 0.125f * 1.4426950408889634f;
        int n4 = ROWS * D_MODEL / 4;
        conv_f16<<<(n4 + 255) / 256, 256>>>(x, xf, n4, 0, 1.0f);
        int w1n4 = 3 * D_MODEL * D_MODEL / 4;
        conv_f16<<<(w1n4 + 255) / 256, 256>>>(Wqkv, w1f, w1n4,
                                              D_MODEL * D_MODEL / 4, QSCALE);
        int w2n4 = D_MODEL * D_MODEL / 4;
        conv_f16<<<(w2n4 + 255) / 256, 256>>>(Wout, w2f, w2n4, 0, 1.0f);
    }

    // 1) QKV projection -> fp16 qkv
    gemm_f16<true><<<dim3(3 * D_MODEL / 128, ROWS / 128), 256, GEMM_SMEM>>>(
        xf, w1f, nullptr, qkvf, ROWS, 3 * D_MODEL, D_MODEL);

    // 2) fp16 tensor-core causal flash attention (LPT order) -> yf
    attn_tc<<<dim3(SEQ / 128, NUM_HEADS, BATCH), 256, AT_SMEM>>>(qkvf, yf);

    // 3) Output projection -> fp32 out
    gemm_f16<false><<<dim3(D_MODEL / 128, ROWS / 128), 256, GEMM_SMEM>>>(
        yf, w2f, out, nullptr, ROWS, D_MODEL, D_MODEL);
}